// round 12
// baseline (speedup 1.0000x reference)
#include <cuda_runtime.h>
#include <cuda_bf16.h>
#include <math.h>
#include <stdint.h>

// ---------------- problem constants ----------------
#define BB   16
#define SS   408
#define DD   512
#define LL   10
#define FFN  2048
#define HH   8
#define DH   64
#define CHK  68
#define NCHUNK (SS/CHK)     // 6
#define MROWS (BB*SS)       // 6528
#define EPS  1e-5f

// ---------------- scratch (no allocations allowed) ----------------
__device__ __align__(16) float g_scratch[(size_t)5 * MROWS * DD];
__device__ __align__(16) float g_chunkS[(size_t)BB * HH * NCHUNK * DH * DH];
__device__ __align__(16) __nv_bfloat16 g_act[(size_t)12 * MROWS * DD];
#define W5  ((size_t)LL * DD * DD)
#define WF  ((size_t)LL * DD * FFN)
__device__ __align__(16) __nv_bfloat16 g_wts[10 * W5 + 4 * WF];
__device__ __align__(16) float g_bias[(size_t)LL * 2048];
__device__ __align__(16) float g_rotcs[SS * 32];
__device__ __align__(16) float g_rotsn[SS * 32];

// ================= PTX helpers (family-portable: sm_80+) =================
__device__ __forceinline__ uint32_t smem_u32(const void* p) {
    uint32_t a;
    asm("{ .reg .u64 t; cvta.to.shared.u64 t, %1; cvt.u32.u64 %0, t; }"
        : "=r"(a) : "l"(p));
    return a;
}
__device__ __forceinline__ void cp16(uint32_t dst, const void* src) {
    asm volatile("cp.async.cg.shared.global [%0], [%1], 16;"
                 :: "r"(dst), "l"(src));
}
#define CP_COMMIT() asm volatile("cp.async.commit_group;" ::: "memory")
#define CP_WAIT(n)  asm volatile("cp.async.wait_group %0;" :: "n"(n) : "memory")

__device__ __forceinline__ void ldsm4(uint32_t* r, uint32_t addr) {
    asm volatile("ldmatrix.sync.aligned.m8n8.x4.shared.b16 {%0,%1,%2,%3}, [%4];"
                 : "=r"(r[0]), "=r"(r[1]), "=r"(r[2]), "=r"(r[3]) : "r"(addr));
}
__device__ __forceinline__ void mma_bf16(float* c, const uint32_t* a,
                                         uint32_t b0, uint32_t b1) {
    asm volatile(
        "mma.sync.aligned.m16n8k16.row.col.f32.bf16.bf16.f32 "
        "{%0,%1,%2,%3}, {%4,%5,%6,%7}, {%8,%9}, {%0,%1,%2,%3};"
        : "+f"(c[0]), "+f"(c[1]), "+f"(c[2]), "+f"(c[3])
        : "r"(a[0]), "r"(a[1]), "r"(a[2]), "r"(a[3]), "r"(b0), "r"(b1));
}
__device__ __forceinline__ void bsplit(float f, __nv_bfloat16& h, __nv_bfloat16& l) {
    h = __float2bfloat16(f);
    l = __float2bfloat16(f - __bfloat162float(h));
}

// ------- weight transpose + bf16 hi/lo split: 5 square mats fused -------
__global__ void wconv5_kernel(const float* __restrict__ Wq, const float* __restrict__ Wk,
                              const float* __restrict__ Wv, const float* __restrict__ Wg,
                              const float* __restrict__ Wo,
                              __nv_bfloat16* __restrict__ qkvg_h, __nv_bfloat16* __restrict__ qkvg_l,
                              __nv_bfloat16* __restrict__ wo_h,   __nv_bfloat16* __restrict__ wo_l)
{
    __shared__ float t[32][33];
    int z = blockIdx.z;
    int m = z / LL, l = z - m * LL;
    const float* S = (m == 0) ? Wq : (m == 1) ? Wk : (m == 2) ? Wv : (m == 3) ? Wg : Wo;
    const float* s = S + (size_t)l * DD * DD;
    int n0 = blockIdx.x * 32, k0 = blockIdx.y * 32;
    int tx = threadIdx.x, ty = threadIdx.y;
    #pragma unroll
    for (int r = ty; r < 32; r += 8)
        t[r][tx] = s[(size_t)(k0 + r) * DD + n0 + tx];
    __syncthreads();
    __nv_bfloat16* hi;
    __nv_bfloat16* lo;
    size_t dbase;
    if (m < 4) {
        hi = qkvg_h; lo = qkvg_l;
        dbase = (size_t)l * 2048 * DD + (size_t)m * 512 * DD;
    } else {
        hi = wo_h; lo = wo_l;
        dbase = (size_t)l * DD * DD;
    }
    #pragma unroll
    for (int r = ty; r < 32; r += 8) {
        float x = t[tx][r];
        __nv_bfloat16 h, lw;
        bsplit(x, h, lw);
        size_t o = dbase + (size_t)(n0 + r) * DD + k0 + tx;
        hi[o] = h;
        lo[o] = lw;
    }
}

// ---------------- generic weight transpose (ff mats) --------------
__global__ void wconv_kernel(const float* __restrict__ src,
                             __nv_bfloat16* __restrict__ hi,
                             __nv_bfloat16* __restrict__ lo,
                             int K, int N)
{
    __shared__ float t[32][33];
    int n0 = blockIdx.x * 32, k0 = blockIdx.y * 32;
    const float* s = src + (size_t)blockIdx.z * K * N;
    int tx = threadIdx.x, ty = threadIdx.y;
    #pragma unroll
    for (int r = ty; r < 32; r += 8)
        t[r][tx] = s[(size_t)(k0 + r) * N + n0 + tx];
    __syncthreads();
    size_t dbase = (size_t)blockIdx.z * N * K;
    #pragma unroll
    for (int r = ty; r < 32; r += 8) {
        float x = t[tx][r];
        __nv_bfloat16 h, lw;
        bsplit(x, h, lw);
        size_t o = dbase + (size_t)(n0 + r) * K + k0 + tx;
        hi[o] = h;
        lo[o] = lw;
    }
}

// ---- fused: embedding gather + LN(layer0) split + bias pack + rot tables ----
__global__ void embed_ln_kernel(const int* __restrict__ tokens,
                                const float* __restrict__ emb,
                                const float* __restrict__ w,
                                const float* __restrict__ b,
                                float* __restrict__ x,
                                __nv_bfloat16* __restrict__ hi,
                                __nv_bfloat16* __restrict__ lo,
                                const float* __restrict__ bq,
                                const float* __restrict__ bk,
                                const float* __restrict__ bv,
                                const float* __restrict__ bg,
                                float* __restrict__ biasPacked)
{
    int row = blockIdx.x;
    int tid = threadIdx.x;                 // 256
    int tok = tokens[row];
    const float* src = emb + (size_t)tok * DD;
    float v0 = src[tid], v1 = src[tid + 256];
    size_t base = (size_t)row * DD;
    x[base + tid]       = v0;
    x[base + tid + 256] = v1;

    float s = v0 + v1, ss = v0*v0 + v1*v1;
    __shared__ float rs[8], rss[8];
    #pragma unroll
    for (int o = 16; o; o >>= 1) {
        s  += __shfl_xor_sync(0xffffffffu, s,  o);
        ss += __shfl_xor_sync(0xffffffffu, ss, o);
    }
    if ((tid & 31) == 0) { rs[tid >> 5] = s; rss[tid >> 5] = ss; }
    __syncthreads();
    float tot = 0.f, tots = 0.f;
    #pragma unroll
    for (int i = 0; i < 8; i++) { tot += rs[i]; tots += rss[i]; }
    float mean = tot * (1.f / DD);
    float var  = tots * (1.f / DD) - mean * mean;
    float rstd = rsqrtf(var + EPS);
    float o0 = (v0 - mean) * rstd * w[tid]       + b[tid];
    float o1 = (v1 - mean) * rstd * w[tid + 256] + b[tid + 256];
    __nv_bfloat16 h0, l0, h1, l1;
    bsplit(o0, h0, l0);
    bsplit(o1, h1, l1);
    hi[base + tid]       = h0;
    hi[base + tid + 256] = h1;
    lo[base + tid]       = l0;
    lo[base + tid + 256] = l1;

    if (row < (LL * 2048) / 512) {
        #pragma unroll
        for (int t = 0; t < 2; t++) {
            int gi = row * 512 + tid + t * 256;
            int l = gi >> 11, r = gi & 2047;
            int wsel = r >> 9, d = r & 511;
            const float* sp = (wsel == 0) ? bq : (wsel == 1) ? bk : (wsel == 2) ? bv : bg;
            biasPacked[gi] = sp[l * 512 + d];
        }
    }
    if (row < SS && tid < 32) {
        float inv = powf(10000.f, -2.f * (float)tid / 64.f);
        float ang = (float)row * inv;
        float sn, cs;
        sincosf(ang, &sn, &cs);
        g_rotcs[row * 32 + tid] = cs;
        g_rotsn[row * 32 + tid] = sn;
    }
}

// ---------------- layer norm -> bf16 hi/lo split ----------------
__global__ void layernorm_split_kernel(const float* __restrict__ x,
                                       const float* __restrict__ w,
                                       const float* __restrict__ b,
                                       __nv_bfloat16* __restrict__ hi,
                                       __nv_bfloat16* __restrict__ lo)
{
    int row = blockIdx.x;
    int tid = threadIdx.x;                 // 256
    const float* xr = x + (size_t)row * DD;
    float v0 = xr[tid], v1 = xr[tid + 256];
    float s = v0 + v1, ss = v0*v0 + v1*v1;
    __shared__ float rs[8], rss[8];
    #pragma unroll
    for (int o = 16; o; o >>= 1) {
        s  += __shfl_xor_sync(0xffffffffu, s,  o);
        ss += __shfl_xor_sync(0xffffffffu, ss, o);
    }
    if ((tid & 31) == 0) { rs[tid >> 5] = s; rss[tid >> 5] = ss; }
    __syncthreads();
    float tot = 0.f, tots = 0.f;
    #pragma unroll
    for (int i = 0; i < 8; i++) { tot += rs[i]; tots += rss[i]; }
    float mean = tot * (1.f / DD);
    float var  = tots * (1.f / DD) - mean * mean;
    float rstd = rsqrtf(var + EPS);
    float o0 = (v0 - mean) * rstd * w[tid]       + b[tid];
    float o1 = (v1 - mean) * rstd * w[tid + 256] + b[tid + 256];
    size_t base = (size_t)row * DD;
    __nv_bfloat16 h0, l0, h1, l1;
    bsplit(o0, h0, l0);
    bsplit(o1, h1, l1);
    hi[base + tid]       = h0;
    hi[base + tid + 256] = h1;
    lo[base + tid]       = l0;
    lo[base + tid + 256] = l1;
}

// ------ tensor-core GEMM (bf16 3-term, BM=128 BN=64 BK=32, 3 CTA/SM) ------
#define APITCH 80
#define SA_H 0
#define SA_L 10240
#define SB_H 20480
#define SB_L 25600
#define GSTG 30720
#define GEMM_SMEM (2 * GSTG)

__global__ void __launch_bounds__(256, 3)
tc_gemm(const __nv_bfloat16* __restrict__ Ah,
        const __nv_bfloat16* __restrict__ Al,
        const __nv_bfloat16* __restrict__ Bh,
        const __nv_bfloat16* __restrict__ Bl,
        const float* __restrict__ bias,
        float* __restrict__ C,
        __nv_bfloat16* __restrict__ Ch,
        __nv_bfloat16* __restrict__ Cl,
        int K, int N, int epi)
{
    extern __shared__ char sm[];
    uint32_t sb = smem_u32(sm);
    int tid = threadIdx.x;
    int lane = tid & 31, wid = tid >> 5;
    int m0 = blockIdx.y * 128, n0 = blockIdx.x * 64;
    int wm = wid & 3, wn = wid >> 2;      // warp tile 32(M) x 32(N)

    int nst = K >> 5;                      // BK = 32

    float acc[8][4];
    #pragma unroll
    for (int i = 0; i < 8; i++)
        #pragma unroll
        for (int j = 0; j < 4; j++) acc[i][j] = 0.f;

    uint32_t rowoff = (uint32_t)((lane & 15) * APITCH + (lane >> 4) * 16);

    auto issue = [&](int s, int buf) {
        uint32_t dst = sb + buf * GSTG;
        int k0 = s << 5;
        #pragma unroll
        for (int it = 0; it < 2; it++) {
            int c = tid + it * 256;          // 0..511 (A: 128 rows x 4 segs)
            int row = c >> 2, seg = c & 3;
            uint32_t doff = (uint32_t)(row * APITCH + seg * 16);
            size_t aoff = (size_t)(m0 + row) * K + k0 + seg * 8;
            cp16(dst + SA_H + doff, Ah + aoff);
            cp16(dst + SA_L + doff, Al + aoff);
        }
        {
            int c = tid;                     // 0..255 (B: 64 rows x 4 segs)
            int row = c >> 2, seg = c & 3;
            uint32_t doff = (uint32_t)(row * APITCH + seg * 16);
            size_t boff = (size_t)(n0 + row) * K + k0 + seg * 8;
            cp16(dst + SB_H + doff, Bh + boff);
            cp16(dst + SB_L + doff, Bl + boff);
        }
    };

    issue(0, 0);
    CP_COMMIT();

    for (int s = 0; s < nst; s++) {
        int buf = s & 1;
        if (s + 1 < nst) {
            issue(s + 1, buf ^ 1);
            CP_COMMIT();
            CP_WAIT(1);
        } else {
            CP_WAIT(0);
        }
        __syncthreads();

        uint32_t base  = sb + buf * GSTG;
        uint32_t abase = base + (uint32_t)(wm * 32 * APITCH) + rowoff;
        uint32_t bbase = base + SB_H + (uint32_t)(wn * 32 * APITCH) + rowoff;

        #pragma unroll
        for (int kst = 0; kst < 2; kst++) {
            uint32_t koff = (uint32_t)(kst * 32);
            uint32_t bh[2][4], bl[2][4];
            #pragma unroll
            for (int nb = 0; nb < 2; nb++) {
                ldsm4(bh[nb], bbase + nb * (16 * APITCH) + koff);
                ldsm4(bl[nb], bbase + (SB_L - SB_H) + nb * (16 * APITCH) + koff);
            }
            #pragma unroll
            for (int mt = 0; mt < 2; mt++) {
                uint32_t ah[4], al[4];
                ldsm4(ah, abase + SA_H + mt * (16 * APITCH) + koff);
                ldsm4(al, abase + SA_L + mt * (16 * APITCH) + koff);
                #pragma unroll
                for (int nt = 0; nt < 4; nt++)
                    mma_bf16(acc[mt * 4 + nt], ah,
                             bh[nt >> 1][nt & 1], bh[nt >> 1][(nt & 1) + 2]);
                #pragma unroll
                for (int nt = 0; nt < 4; nt++)
                    mma_bf16(acc[mt * 4 + nt], al,
                             bh[nt >> 1][nt & 1], bh[nt >> 1][(nt & 1) + 2]);
                #pragma unroll
                for (int nt = 0; nt < 4; nt++)
                    mma_bf16(acc[mt * 4 + nt], ah,
                             bl[nt >> 1][nt & 1], bl[nt >> 1][(nt & 1) + 2]);
            }
        }
        __syncthreads();
    }

    // -------- epilogue --------
    bool fused = (epi == 4);
    int which = n0 >> 9;
    float* Cb = C;
    int ldc = N, ncol0 = n0;
    if (fused) {
        Cb = C + (size_t)which * ((size_t)MROWS * 512);
        ldc = 512;
        ncol0 = n0 & 511;
    }
    bool dosilu = (epi == 1) || (epi == 3) || (fused && which == 3);

    int r_lane = lane >> 2;
    int c_lane = (lane & 3) * 2;
    #pragma unroll
    for (int mt = 0; mt < 2; mt++) {
        int r0 = m0 + wm * 32 + mt * 16 + r_lane;
        int r1 = r0 + 8;
        #pragma unroll
        for (int nt = 0; nt < 4; nt++) {
            float* a = acc[mt * 4 + nt];
            int ncb = wn * 32 + nt * 8 + c_lane;   // 0..63 in block
            float b0 = bias[n0 + ncb], b1 = bias[n0 + ncb + 1];
            float x0 = a[0] + b0, x1 = a[1] + b1;
            float y0 = a[2] + b0, y1 = a[3] + b1;
            if (dosilu) {
                x0 = x0 / (1.f + expf(-x0));
                x1 = x1 / (1.f + expf(-x1));
                y0 = y0 / (1.f + expf(-y0));
                y1 = y1 / (1.f + expf(-y1));
            }
            int nn = ncol0 + ncb;
            if (epi == 3) {
                __nv_bfloat162 h0 = __floats2bfloat162_rn(x0, x1);
                __nv_bfloat162 h1 = __floats2bfloat162_rn(y0, y1);
                float2 f0 = __bfloat1622float2(h0);
                float2 f1 = __bfloat1622float2(h1);
                __nv_bfloat162 l0 = __floats2bfloat162_rn(x0 - f0.x, x1 - f0.y);
                __nv_bfloat162 l1 = __floats2bfloat162_rn(y0 - f1.x, y1 - f1.y);
                *(__nv_bfloat162*)(Ch + (size_t)r0 * N + nn) = h0;
                *(__nv_bfloat162*)(Cl + (size_t)r0 * N + nn) = l0;
                *(__nv_bfloat162*)(Ch + (size_t)r1 * N + nn) = h1;
                *(__nv_bfloat162*)(Cl + (size_t)r1 * N + nn) = l1;
            } else {
                float* p0 = Cb + (size_t)r0 * ldc + nn;
                float* p1 = Cb + (size_t)r1 * ldc + nn;
                if (epi == 2) {
                    float2 c0 = *(float2*)p0;
                    float2 c1 = *(float2*)p1;
                    x0 += c0.x; x1 += c0.y;
                    y0 += c1.x; y1 += c1.y;
                }
                *(float2*)p0 = make_float2(x0, x1);
                *(float2*)p1 = make_float2(y0, y1);
            }
        }
    }
}

// ======== retention phase 1 (HMMA, 512 threads: 1 MMA tile per warp) ========
__global__ void __launch_bounds__(512)
ret_phase1(const float* __restrict__ k, const float* __restrict__ v,
           float* __restrict__ chunkS)
{
    __shared__ __nv_bfloat16 kth[64 * 80], ktl[64 * 80];
    __shared__ __nv_bfloat16 vth[64 * 80], vtl[64 * 80];
    __shared__ float gpow[CHK + 1];

    int z  = blockIdx.x;
    int bh = z / NCHUNK, c = z - bh * NCHUNK;
    int b  = bh >> 3, hh = bh & 7;
    int tid = threadIdx.x;
    float gamma = 1.f - exp2f(-5.f - (float)hh);
    if (tid <= CHK) gpow[tid] = powf(gamma, (float)tid);
    __nv_bfloat16 z16 = __float2bfloat16(0.f);
    for (int t = tid; t < 64 * 12; t += 512) {
        int d = t / 12, j = 68 + (t % 12);
        int idx = d * 80 + j;
        kth[idx] = z16; ktl[idx] = z16;
        vth[idx] = z16; vtl[idx] = z16;
    }
    __syncthreads();

    int base = ((b * SS + c * CHK) * HH + hh) * DH;
    for (int i = tid; i < CHK * DH; i += 512) {
        int r = i >> 6, d = i & 63;
        int g = base + r * DD + d;
        int spos = c * CHK + r;
        int j = d & 31;
        float cs = g_rotcs[spos * 32 + j];
        float sn = g_rotsn[spos * 32 + j];
        float ka = k[g];
        float kb = (d < 32) ? -k[g + 32] : k[g - 32];
        float kv = (ka * cs + kb * sn) * 0.125f * gpow[CHK - 1 - r];
        __nv_bfloat16 h, l;
        bsplit(kv, h, l);
        kth[d * 80 + r] = h;
        ktl[d * 80 + r] = l;
        float vv = v[g];
        bsplit(vv, h, l);
        vth[d * 80 + r] = h;
        vtl[d * 80 + r] = l;
    }
    __syncthreads();

    uint32_t kthA = smem_u32(kth), ktlA = smem_u32(ktl);
    uint32_t vthA = smem_u32(vth), vtlA = smem_u32(vtl);
    int lane = tid & 31, wid = tid >> 5;   // 16 warps
    uint32_t rowoff = (uint32_t)((lane & 15) * 160 + (lane >> 4) * 16);
    float* out = chunkS + (size_t)z * (DH * DH);

    {
        int u = wid;
        int mt = u >> 2, nb = u & 3;
        float acc[2][4] = {};
        #pragma unroll
        for (int kst = 0; kst < 5; kst++) {
            uint32_t koff = (uint32_t)(kst * 32);
            uint32_t ah[4], al[4], bh4[4], bl4[4];
            ldsm4(ah, kthA + mt * (16 * 160) + rowoff + koff);
            ldsm4(al, ktlA + mt * (16 * 160) + rowoff + koff);
            ldsm4(bh4, vthA + nb * (16 * 160) + rowoff + koff);
            ldsm4(bl4, vtlA + nb * (16 * 160) + rowoff + koff);
            #pragma unroll
            for (int half = 0; half < 2; half++) {
                mma_bf16(acc[half], ah, bh4[half], bh4[half + 2]);
                mma_bf16(acc[half], al, bh4[half], bh4[half + 2]);
                mma_bf16(acc[half], ah, bl4[half], bl4[half + 2]);
            }
        }
        int r0 = mt * 16 + (lane >> 2);
        #pragma unroll
        for (int half = 0; half < 2; half++) {
            int c0 = nb * 16 + half * 8 + (lane & 3) * 2;
            out[r0 * 64 + c0]           = acc[half][0];
            out[r0 * 64 + c0 + 1]       = acc[half][1];
            out[(r0 + 8) * 64 + c0]     = acc[half][2];
            out[(r0 + 8) * 64 + c0 + 1] = acc[half][3];
        }
    }
}

// ===== retention phase 2 (FFMA overlay, 512 thr) + FUSED gnorm*gate =====
#define KT_PITCH 72
#define RET2_FLOATS (2 * CHK * DH + DH * DH + 4624)
__global__ void __launch_bounds__(512)
ret_phase2(const float* __restrict__ q, const float* __restrict__ k,
           const float* __restrict__ v, const float* __restrict__ chunkS,
           const float* __restrict__ gnw, const float* __restrict__ gnb,
           const float* __restrict__ gate,
           __nv_bfloat16* __restrict__ ghi, __nv_bfloat16* __restrict__ glo)
{
    extern __shared__ float smf[];
    float* sq    = smf;
    float* sv    = sq + CHK * DH;
    float* st    = sv + CHK * DH;
    float* skT   = st + DH * DH;
    float* inner = skT;
    __shared__ float gpow[CHK + 1];

    int z  = blockIdx.x;
    int bh = z / NCHUNK, c = z - bh * NCHUNK;
    int b  = bh >> 3, hh = bh & 7;
    int tid = threadIdx.x;
    float gamma = 1.f - exp2f(-5.f - (float)hh);
    if (tid <= CHK) gpow[tid] = powf(gamma, (float)tid);
    __syncthreads();
    float chunk_dec = gpow[CHK];

    int base = ((b * SS + c * CHK) * HH + hh) * DH;
    for (int i = tid; i < CHK * DH; i += 512) {
        int r = i >> 6, d = i & 63;
        int g = base + r * DD + d;
        int spos = c * CHK + r;
        int j = d & 31;
        float cs = g_rotcs[spos * 32 + j];
        float sn = g_rotsn[spos * 32 + j];
        float qa = q[g], ka = k[g];
        float qb, kb;
        if (d < 32) { qb = -q[g + 32]; kb = -k[g + 32]; }
        else        { qb =  q[g - 32]; kb =  k[g - 32]; }
        sq[i] = qa * cs + qb * sn;
        skT[d * KT_PITCH + r] = (ka * cs + kb * sn) * 0.125f;
        sv[i] = v[g];
    }
    {
        const float* Sbase = chunkS + (size_t)(bh * NCHUNK) * (DH * DH);
        #pragma unroll
        for (int g4 = 0; g4 < 2; g4++) {
            int idx = tid * 8 + g4 * 4;
            float4 acc = make_float4(0.f, 0.f, 0.f, 0.f);
            float w = 1.f;
            for (int cc = c - 1; cc >= 0; cc--) {
                float4 sv4 = *(const float4*)(Sbase + (size_t)cc * (DH * DH) + idx);
                acc.x += w * sv4.x; acc.y += w * sv4.y;
                acc.z += w * sv4.z; acc.w += w * sv4.w;
                w *= chunk_dec;
            }
            *(float4*)(st + idx) = acc;
        }
    }
    __syncthreads();

    float ir[3][4];
    #pragma unroll
    for (int it = 0; it < 3; it++) {
        int e = tid + it * 512;
        if (e < CHK * 17) {
            int i = e / 17, jg = e - i * 17;
            int j0 = jg * 4;
            float4 s = make_float4(0.f, 0.f, 0.f, 0.f);
            if (i >= j0) {
                const float* qi = sq + i * DH;
                #pragma unroll 4
                for (int d4 = 0; d4 < DH; d4 += 4) {
                    float4 qv = *(const float4*)(qi + d4);
                    float4 k0 = *(const float4*)(skT + (d4 + 0) * KT_PITCH + j0);
                    float4 k1 = *(const float4*)(skT + (d4 + 1) * KT_PITCH + j0);
                    float4 k2 = *(const float4*)(skT + (d4 + 2) * KT_PITCH + j0);
                    float4 k3 = *(const float4*)(skT + (d4 + 3) * KT_PITCH + j0);
                    s.x += qv.x*k0.x + qv.y*k1.x + qv.z*k2.x + qv.w*k3.x;
                    s.y += qv.x*k0.y + qv.y*k1.y + qv.z*k2.y + qv.w*k3.y;
                    s.z += qv.x*k0.z + qv.y*k1.z + qv.z*k2.z + qv.w*k3.z;
                    s.w += qv.x*k0.w + qv.y*k1.w + qv.z*k2.w + qv.w*k3.w;
                }
            }
            ir[it][0] = s.x; ir[it][1] = s.y;
            ir[it][2] = s.z; ir[it][3] = s.w;
        }
    }
    __syncthreads();
    #pragma unroll
    for (int it = 0; it < 3; it++) {
        int e = tid + it * 512;
        if (e < CHK * 17) {
            int i = e / 17, jg = e - i * 17;
            int j0 = jg * 4;
            float* out = inner + i * CHK + j0;
            out[0] = (i >= j0)     ? ir[it][0] * gpow[i - j0]     : 0.f;
            out[1] = (i >= j0 + 1) ? ir[it][1] * gpow[i - j0 - 1] : 0.f;
            out[2] = (i >= j0 + 2) ? ir[it][2] * gpow[i - j0 - 2] : 0.f;
            out[3] = (i >= j0 + 3) ? ir[it][3] * gpow[i - j0 - 3] : 0.f;
        }
    }
    __syncthreads();

    #pragma unroll
    for (int kk = 0; kk < 3; kk++) {
        int e = tid + kk * 512;
        if (e >= CHK * 16) break;
        int i = e >> 4, d4 = (e & 15) << 2;
        float4 acc = make_float4(0.f, 0.f, 0.f, 0.f);
        const float* in_i = inner + i * CHK;
        for (int j = 0; j <= i; j++) {
            float w = in_i[j];
            float4 vv = *(const float4*)(sv + j * DH + d4);
            acc.x += w * vv.x; acc.y += w * vv.y;
            acc.z += w * vv.z; acc.w += w * vv.w;
        }
        float4 a2 = make_float4(0.f, 0.f, 0.f, 0.f);
        const float* qi = sq + i * DH;
        #pragma unroll 8
        for (int ee = 0; ee < DH; ee++) {
            float qv = qi[ee];
            float4 sr = *(const float4*)(st + ee * DH + d4);
            a2.x += qv * sr.x; a2.y += qv * sr.y;
            a2.z += qv * sr.z; a2.w += qv * sr.w;
        }
        float cd = gamma * gpow[i];
        acc.x += a2.x * cd; acc.y += a2.y * cd;
        acc.z += a2.z * cd; acc.w += a2.w * cd;

        float lsum = acc.x + acc.y + acc.z + acc.w;
        float lss  = acc.x*acc.x + acc.y*acc.y + acc.z*acc.z + acc.w*acc.w;
        #pragma unroll
        for (int o = 8; o; o >>= 1) {
            lsum += __shfl_xor_sync(0xffffffffu, lsum, o);
            lss  += __shfl_xor_sync(0xffffffffu, lss,  o);
        }
        float mean = lsum * (1.f / DH);
        float var  = lss * (1.f / DH) - mean * mean;
        float rstd = rsqrtf(var + EPS);
        int wi = hh * DH + d4;
        float4 gw = *(const float4*)(gnw + wi);
        float4 gb = *(const float4*)(gnb + wi);
        int gidx = base + i * DD + d4;
        float4 gt = *(const float4*)(gate + gidx);
        float p0 = gt.x * ((acc.x - mean) * rstd * gw.x + gb.x);
        float p1 = gt.y * ((acc.y - mean) * rstd * gw.y + gb.y);
        float p2 = gt.z * ((acc.z - mean) * rstd * gw.z + gb.z);
        float p3 = gt.w * ((acc.w - mean) * rstd * gw.w + gb.w);
        __nv_bfloat162 h0 = __floats2bfloat162_rn(p0, p1);
        __nv_bfloat162 h1 = __floats2bfloat162_rn(p2, p3);
        float2 f0 = __bfloat1622float2(h0);
        float2 f1 = __bfloat1622float2(h1);
        __nv_bfloat162 l0 = __floats2bfloat162_rn(p0 - f0.x, p1 - f0.y);
        __nv_bfloat162 l1 = __floats2bfloat162_rn(p2 - f1.x, p3 - f1.y);
        *(__nv_bfloat162*)(ghi + gidx)     = h0;
        *(__nv_bfloat162*)(ghi + gidx + 2) = h1;
        *(__nv_bfloat162*)(glo + gidx)     = l0;
        *(__nv_bfloat162*)(glo + gidx + 2) = l1;
    }
}

// ---------------- host orchestration ----------------
extern "C" void kernel_launch(void* const* d_in, const int* in_sizes, int n_in,
                              void* d_out, int out_size)
{
    const int*   tokens = (const int*)  d_in[0];
    const float* emb    = (const float*)d_in[1];
    const float* Wq = (const float*)d_in[2],  * bq = (const float*)d_in[3];
    const float* Wk = (const float*)d_in[4],  * bk = (const float*)d_in[5];
    const float* Wv = (const float*)d_in[6],  * bv = (const float*)d_in[7];
    const float* Wg = (const float*)d_in[8],  * bg = (const float*)d_in[9];
    const float* Wo = (const float*)d_in[10], * bo = (const float*)d_in[11];
    const float* gnw  = (const float*)d_in[12], * gnb  = (const float*)d_in[13];
    const float* ln1w = (const float*)d_in[14], * ln1b = (const float*)d_in[15];
    const float* ln2w = (const float*)d_in[16], * ln2b = (const float*)d_in[17];
    const float* w1 = (const float*)d_in[18], * b1 = (const float*)d_in[19];
    const float* w2 = (const float*)d_in[20], * b2 = (const float*)d_in[21];

    float* x = (float*)d_out;

    float* fb = nullptr;
    cudaGetSymbolAddress((void**)&fb, g_scratch);
    const size_t SZ = (size_t)MROWS * DD;
    float* q = fb;                           // q,k,v,gate consecutive (epi4!)

    float* chunkS = nullptr;
    cudaGetSymbolAddress((void**)&chunkS, g_chunkS);

    __nv_bfloat16* ab = nullptr;
    cudaGetSymbolAddress((void**)&ab, g_act);
    __nv_bfloat16* h_hi  = ab;
    __nv_bfloat16* h_lo  = ab + SZ;
    __nv_bfloat16* g_hi  = ab + 2 * SZ;
    __nv_bfloat16* g_lo  = ab + 3 * SZ;
    __nv_bfloat16* ff_hi = ab + 4 * SZ;
    __nv_bfloat16* ff_lo = ab + 8 * SZ;

    __nv_bfloat16* wts = nullptr;
    cudaGetSymbolAddress((void**)&wts, g_wts);
    __nv_bfloat16* qkvg_h = wts;             // [L][2048][512]
    __nv_bfloat16* qkvg_l = wts + 4 * W5;
    __nv_bfloat16* wo_h   = wts + 8 * W5;
    __nv_bfloat16* wo_l   = wts + 9 * W5;
    __nv_bfloat16* w1_h   = wts + 10 * W5;
    __nv_bfloat16* w1_l   = wts + 10 * W5 + WF;
    __nv_bfloat16* w2_h   = wts + 10 * W5 + 2 * WF;
    __nv_bfloat16* w2_l   = wts + 10 * W5 + 3 * WF;

    float* biasP = nullptr;
    cudaGetSymbolAddress((void**)&biasP, g_bias);

    const int RET2_SMEM = RET2_FLOATS * (int)sizeof(float);
    cudaFuncSetAttribute(ret_phase2,
                         cudaFuncAttributeMaxDynamicSharedMemorySize, RET2_SMEM);
    cudaFuncSetAttribute(tc_gemm,
                         cudaFuncAttributeMaxDynamicSharedMemorySize, GEMM_SMEM);

    dim3 wb(32, 8);
    dim3 gemmQKVG(2048 / 64, MROWS / 128);   // (32, 51)
    dim3 gemmO(DD / 64, MROWS / 128);        // (8, 51)
    dim3 gemmF1(FFN / 64, MROWS / 128);      // (32, 51)
    dim3 gemmF2(DD / 64, MROWS / 128);       // (8, 51)
    const int NRET = BB * HH * NCHUNK;       // 768

    for (int l = 0; l < LL; l++) {
        const size_t oQW = (size_t)l * 2048 * DD;
        const size_t oW  = (size_t)l * DD * DD;
        const size_t oF  = (size_t)l * DD * FFN;
        const size_t ob  = (size_t)l * DD;
        const size_t obf = (size_t)l * FFN;

        if (l == 0) {
            wconv5_kernel<<<dim3(16, 16, 5 * LL), wb>>>(Wq, Wk, Wv, Wg, Wo,
                                                        qkvg_h, qkvg_l, wo_h, wo_l);
            embed_ln_kernel<<<MROWS, 256>>>(tokens, emb, ln1w, ln1b, x, h_hi, h_lo,
                                            bq, bk, bv, bg, biasP);
        } else {
            layernorm_split_kernel<<<MROWS, 256>>>(x, ln1w + ob, ln1b + ob, h_hi, h_lo);
        }

        tc_gemm<<<gemmQKVG, 256, GEMM_SMEM>>>(h_hi, h_lo, qkvg_h + oQW, qkvg_l + oQW,
                                              biasP + (size_t)l * 2048, q,
                                              nullptr, nullptr, DD, 2048, 4);

        ret_phase1<<<NRET, 512>>>(q + SZ, q + 2 * SZ, chunkS);
        ret_phase2<<<NRET, 512, RET2_SMEM>>>(q, q + SZ, q + 2 * SZ, chunkS,
                                             gnw + ob, gnb + ob, q + 3 * SZ,
                                             g_hi, g_lo);

        tc_gemm<<<gemmO, 256, GEMM_SMEM>>>(g_hi, g_lo, wo_h + oW, wo_l + oW,
                                           bo + ob, x, nullptr, nullptr, DD, DD, 2);

        if (l == 0) {
            wconv_kernel<<<dim3(FFN / 32, DD / 32, LL), wb>>>(w1, w1_h, w1_l, DD, FFN);
            wconv_kernel<<<dim3(DD / 32, FFN / 32, LL), wb>>>(w2, w2_h, w2_l, FFN, DD);
        }

        layernorm_split_kernel<<<MROWS, 256>>>(x, ln2w + ob, ln2b + ob, h_hi, h_lo);

        tc_gemm<<<gemmF1, 256, GEMM_SMEM>>>(h_hi, h_lo, w1_h + oF, w1_l + oF,
                                            b1 + obf, nullptr, ff_hi, ff_lo,
                                            DD, FFN, 3);
        tc_gemm<<<gemmF2, 256, GEMM_SMEM>>>(ff_hi, ff_lo, w2_h + oF, w2_l + oF,
                                            b2 + ob, x, nullptr, nullptr,
                                            FFN, DD, 2);
    }
}

// round 13
// speedup vs baseline: 1.0602x; 1.0602x over previous
#include <cuda_runtime.h>
#include <cuda_bf16.h>
#include <math.h>
#include <stdint.h>

// ---------------- problem constants ----------------
#define BB   16
#define SS   408
#define DD   512
#define LL   10
#define FFN  2048
#define HH   8
#define DH   64
#define CHK  68
#define NCHUNK (SS/CHK)     // 6
#define MROWS (BB*SS)       // 6528
#define EPS  1e-5f

// ---------------- scratch (no allocations allowed) ----------------
__device__ __align__(16) float g_scratch[(size_t)5 * MROWS * DD];
__device__ __align__(16) float g_chunkS[(size_t)BB * HH * NCHUNK * DH * DH];
__device__ __align__(16) __nv_bfloat16 g_act[(size_t)12 * MROWS * DD];
#define W5  ((size_t)LL * DD * DD)
#define WF  ((size_t)LL * DD * FFN)
__device__ __align__(16) __nv_bfloat16 g_wts[10 * W5 + 4 * WF];
__device__ __align__(16) float g_bias[(size_t)LL * 2048];
__device__ __align__(16) float g_rotcs[SS * 32];
__device__ __align__(16) float g_rotsn[SS * 32];

// ================= PTX helpers (family-portable: sm_80+) =================
__device__ __forceinline__ uint32_t smem_u32(const void* p) {
    uint32_t a;
    asm("{ .reg .u64 t; cvta.to.shared.u64 t, %1; cvt.u32.u64 %0, t; }"
        : "=r"(a) : "l"(p));
    return a;
}
__device__ __forceinline__ void cp16(uint32_t dst, const void* src) {
    asm volatile("cp.async.cg.shared.global [%0], [%1], 16;"
                 :: "r"(dst), "l"(src));
}
#define CP_COMMIT() asm volatile("cp.async.commit_group;" ::: "memory")
#define CP_WAIT(n)  asm volatile("cp.async.wait_group %0;" :: "n"(n) : "memory")

__device__ __forceinline__ void ldsm4(uint32_t* r, uint32_t addr) {
    asm volatile("ldmatrix.sync.aligned.m8n8.x4.shared.b16 {%0,%1,%2,%3}, [%4];"
                 : "=r"(r[0]), "=r"(r[1]), "=r"(r[2]), "=r"(r[3]) : "r"(addr));
}
__device__ __forceinline__ void mma_bf16(float* c, const uint32_t* a,
                                         uint32_t b0, uint32_t b1) {
    asm volatile(
        "mma.sync.aligned.m16n8k16.row.col.f32.bf16.bf16.f32 "
        "{%0,%1,%2,%3}, {%4,%5,%6,%7}, {%8,%9}, {%0,%1,%2,%3};"
        : "+f"(c[0]), "+f"(c[1]), "+f"(c[2]), "+f"(c[3])
        : "r"(a[0]), "r"(a[1]), "r"(a[2]), "r"(a[3]), "r"(b0), "r"(b1));
}
__device__ __forceinline__ void bsplit(float f, __nv_bfloat16& h, __nv_bfloat16& l) {
    h = __float2bfloat16(f);
    l = __float2bfloat16(f - __bfloat162float(h));
}

// ------- weight transpose + bf16 hi/lo split: 5 square mats fused -------
__global__ void wconv5_kernel(const float* __restrict__ Wq, const float* __restrict__ Wk,
                              const float* __restrict__ Wv, const float* __restrict__ Wg,
                              const float* __restrict__ Wo,
                              __nv_bfloat16* __restrict__ qkvg_h, __nv_bfloat16* __restrict__ qkvg_l,
                              __nv_bfloat16* __restrict__ wo_h,   __nv_bfloat16* __restrict__ wo_l)
{
    __shared__ float t[32][33];
    int z = blockIdx.z;
    int m = z / LL, l = z - m * LL;
    const float* S = (m == 0) ? Wq : (m == 1) ? Wk : (m == 2) ? Wv : (m == 3) ? Wg : Wo;
    const float* s = S + (size_t)l * DD * DD;
    int n0 = blockIdx.x * 32, k0 = blockIdx.y * 32;
    int tx = threadIdx.x, ty = threadIdx.y;
    #pragma unroll
    for (int r = ty; r < 32; r += 8)
        t[r][tx] = s[(size_t)(k0 + r) * DD + n0 + tx];
    __syncthreads();
    __nv_bfloat16* hi;
    __nv_bfloat16* lo;
    size_t dbase;
    if (m < 4) {
        hi = qkvg_h; lo = qkvg_l;
        dbase = (size_t)l * 2048 * DD + (size_t)m * 512 * DD;
    } else {
        hi = wo_h; lo = wo_l;
        dbase = (size_t)l * DD * DD;
    }
    #pragma unroll
    for (int r = ty; r < 32; r += 8) {
        float x = t[tx][r];
        __nv_bfloat16 h, lw;
        bsplit(x, h, lw);
        size_t o = dbase + (size_t)(n0 + r) * DD + k0 + tx;
        hi[o] = h;
        lo[o] = lw;
    }
}

// ---------------- generic weight transpose (ff mats) --------------
__global__ void wconv_kernel(const float* __restrict__ src,
                             __nv_bfloat16* __restrict__ hi,
                             __nv_bfloat16* __restrict__ lo,
                             int K, int N)
{
    __shared__ float t[32][33];
    int n0 = blockIdx.x * 32, k0 = blockIdx.y * 32;
    const float* s = src + (size_t)blockIdx.z * K * N;
    int tx = threadIdx.x, ty = threadIdx.y;
    #pragma unroll
    for (int r = ty; r < 32; r += 8)
        t[r][tx] = s[(size_t)(k0 + r) * N + n0 + tx];
    __syncthreads();
    size_t dbase = (size_t)blockIdx.z * N * K;
    #pragma unroll
    for (int r = ty; r < 32; r += 8) {
        float x = t[tx][r];
        __nv_bfloat16 h, lw;
        bsplit(x, h, lw);
        size_t o = dbase + (size_t)(n0 + r) * K + k0 + tx;
        hi[o] = h;
        lo[o] = lw;
    }
}

// ---- fused: embedding gather + LN(layer0) split + bias pack + rot tables ----
__global__ void embed_ln_kernel(const int* __restrict__ tokens,
                                const float* __restrict__ emb,
                                const float* __restrict__ w,
                                const float* __restrict__ b,
                                float* __restrict__ x,
                                __nv_bfloat16* __restrict__ hi,
                                __nv_bfloat16* __restrict__ lo,
                                const float* __restrict__ bq,
                                const float* __restrict__ bk,
                                const float* __restrict__ bv,
                                const float* __restrict__ bg,
                                float* __restrict__ biasPacked)
{
    int row = blockIdx.x;
    int tid = threadIdx.x;                 // 256
    int tok = tokens[row];
    const float* src = emb + (size_t)tok * DD;
    float v0 = src[tid], v1 = src[tid + 256];
    size_t base = (size_t)row * DD;
    x[base + tid]       = v0;
    x[base + tid + 256] = v1;

    float s = v0 + v1, ss = v0*v0 + v1*v1;
    __shared__ float rs[8], rss[8];
    #pragma unroll
    for (int o = 16; o; o >>= 1) {
        s  += __shfl_xor_sync(0xffffffffu, s,  o);
        ss += __shfl_xor_sync(0xffffffffu, ss, o);
    }
    if ((tid & 31) == 0) { rs[tid >> 5] = s; rss[tid >> 5] = ss; }
    __syncthreads();
    float tot = 0.f, tots = 0.f;
    #pragma unroll
    for (int i = 0; i < 8; i++) { tot += rs[i]; tots += rss[i]; }
    float mean = tot * (1.f / DD);
    float var  = tots * (1.f / DD) - mean * mean;
    float rstd = rsqrtf(var + EPS);
    float o0 = (v0 - mean) * rstd * w[tid]       + b[tid];
    float o1 = (v1 - mean) * rstd * w[tid + 256] + b[tid + 256];
    __nv_bfloat16 h0, l0, h1, l1;
    bsplit(o0, h0, l0);
    bsplit(o1, h1, l1);
    hi[base + tid]       = h0;
    hi[base + tid + 256] = h1;
    lo[base + tid]       = l0;
    lo[base + tid + 256] = l1;

    if (row < (LL * 2048) / 512) {
        #pragma unroll
        for (int t = 0; t < 2; t++) {
            int gi = row * 512 + tid + t * 256;
            int l = gi >> 11, r = gi & 2047;
            int wsel = r >> 9, d = r & 511;
            const float* sp = (wsel == 0) ? bq : (wsel == 1) ? bk : (wsel == 2) ? bv : bg;
            biasPacked[gi] = sp[l * 512 + d];
        }
    }
    if (row < SS && tid < 32) {
        float inv = powf(10000.f, -2.f * (float)tid / 64.f);
        float ang = (float)row * inv;
        float sn, cs;
        sincosf(ang, &sn, &cs);
        g_rotcs[row * 32 + tid] = cs;
        g_rotsn[row * 32 + tid] = sn;
    }
}

// ---------------- layer norm -> bf16 hi/lo split ----------------
__global__ void layernorm_split_kernel(const float* __restrict__ x,
                                       const float* __restrict__ w,
                                       const float* __restrict__ b,
                                       __nv_bfloat16* __restrict__ hi,
                                       __nv_bfloat16* __restrict__ lo)
{
    int row = blockIdx.x;
    int tid = threadIdx.x;                 // 256
    const float* xr = x + (size_t)row * DD;
    float v0 = xr[tid], v1 = xr[tid + 256];
    float s = v0 + v1, ss = v0*v0 + v1*v1;
    __shared__ float rs[8], rss[8];
    #pragma unroll
    for (int o = 16; o; o >>= 1) {
        s  += __shfl_xor_sync(0xffffffffu, s,  o);
        ss += __shfl_xor_sync(0xffffffffu, ss, o);
    }
    if ((tid & 31) == 0) { rs[tid >> 5] = s; rss[tid >> 5] = ss; }
    __syncthreads();
    float tot = 0.f, tots = 0.f;
    #pragma unroll
    for (int i = 0; i < 8; i++) { tot += rs[i]; tots += rss[i]; }
    float mean = tot * (1.f / DD);
    float var  = tots * (1.f / DD) - mean * mean;
    float rstd = rsqrtf(var + EPS);
    float o0 = (v0 - mean) * rstd * w[tid]       + b[tid];
    float o1 = (v1 - mean) * rstd * w[tid + 256] + b[tid + 256];
    size_t base = (size_t)row * DD;
    __nv_bfloat16 h0, l0, h1, l1;
    bsplit(o0, h0, l0);
    bsplit(o1, h1, l1);
    hi[base + tid]       = h0;
    hi[base + tid + 256] = h1;
    lo[base + tid]       = l0;
    lo[base + tid + 256] = l1;
}

// ------ tensor-core GEMM (bf16 3-term, BN=64 BK=64), templated on M-tiles --
// MT=2: BM=128, 2 CTA/SM (verified R11).  MT=1: BM=64, 3 CTA/SM (small GEMMs)
#define APITCH 144
template<int MT>
__global__ void __launch_bounds__(256, (MT == 2) ? 2 : 3)
tc_gemm(const __nv_bfloat16* __restrict__ Ah,
        const __nv_bfloat16* __restrict__ Al,
        const __nv_bfloat16* __restrict__ Bh,
        const __nv_bfloat16* __restrict__ Bl,
        const float* __restrict__ bias,
        float* __restrict__ C,
        __nv_bfloat16* __restrict__ Ch,
        __nv_bfloat16* __restrict__ Cl,
        int K, int N, int epi)
{
    constexpr int BM   = MT * 64;
    constexpr int SAL  = BM * APITCH;          // bytes per A tensor
    constexpr int SBH  = 2 * SAL;
    constexpr int SBL  = SBH + 64 * APITCH;
    constexpr int GSTG = SBH + 2 * 64 * APITCH;

    extern __shared__ char sm[];
    uint32_t sb = smem_u32(sm);
    int tid = threadIdx.x;
    int lane = tid & 31, wid = tid >> 5;
    int m0 = blockIdx.y * BM, n0 = blockIdx.x * 64;
    int wm = wid & 3, wn = wid >> 2;      // warp tile (16*MT)(M) x 32(N)

    int nst = K >> 6;                      // BK = 64

    float acc[MT * 4][4];
    #pragma unroll
    for (int i = 0; i < MT * 4; i++)
        #pragma unroll
        for (int j = 0; j < 4; j++) acc[i][j] = 0.f;

    uint32_t rowoff = (uint32_t)((lane & 15) * APITCH + (lane >> 4) * 16);

    auto issue = [&](int s, int buf) {
        uint32_t dst = sb + buf * GSTG;
        int k0 = s << 6;
        #pragma unroll
        for (int it = 0; it < 2 * MT; it++) {
            int c = tid + it * 256;          // A: BM rows x 8 segs
            int row = c >> 3, seg = c & 7;
            uint32_t doff = (uint32_t)(row * APITCH + seg * 16);
            size_t aoff = (size_t)(m0 + row) * K + k0 + seg * 8;
            cp16(dst + 0   + doff, Ah + aoff);
            cp16(dst + SAL + doff, Al + aoff);
        }
        #pragma unroll
        for (int it = 0; it < 2; it++) {
            int c = tid + it * 256;          // B: 64 rows x 8 segs
            int row = c >> 3, seg = c & 7;
            uint32_t doff = (uint32_t)(row * APITCH + seg * 16);
            size_t boff = (size_t)(n0 + row) * K + k0 + seg * 8;
            cp16(dst + SBH + doff, Bh + boff);
            cp16(dst + SBL + doff, Bl + boff);
        }
    };

    issue(0, 0);
    CP_COMMIT();

    for (int s = 0; s < nst; s++) {
        int buf = s & 1;
        if (s + 1 < nst) {
            issue(s + 1, buf ^ 1);
            CP_COMMIT();
            CP_WAIT(1);
        } else {
            CP_WAIT(0);
        }
        __syncthreads();

        uint32_t base  = sb + buf * GSTG;
        uint32_t abase = base + (uint32_t)(wm * (16 * MT) * APITCH) + rowoff;
        uint32_t bbase = base + SBH + (uint32_t)(wn * 32 * APITCH) + rowoff;

        #pragma unroll
        for (int kst = 0; kst < 4; kst++) {
            uint32_t koff = (uint32_t)(kst * 32);
            uint32_t bh[2][4], bl[2][4];
            #pragma unroll
            for (int nb = 0; nb < 2; nb++) {
                ldsm4(bh[nb], bbase + nb * (16 * APITCH) + koff);
                ldsm4(bl[nb], bbase + (SBL - SBH) + nb * (16 * APITCH) + koff);
            }
            #pragma unroll
            for (int mt = 0; mt < MT; mt++) {
                uint32_t ah[4], al[4];
                ldsm4(ah, abase + 0   + mt * (16 * APITCH) + koff);
                ldsm4(al, abase + SAL + mt * (16 * APITCH) + koff);
                #pragma unroll
                for (int nt = 0; nt < 4; nt++)
                    mma_bf16(acc[mt * 4 + nt], ah,
                             bh[nt >> 1][nt & 1], bh[nt >> 1][(nt & 1) + 2]);
                #pragma unroll
                for (int nt = 0; nt < 4; nt++)
                    mma_bf16(acc[mt * 4 + nt], al,
                             bh[nt >> 1][nt & 1], bh[nt >> 1][(nt & 1) + 2]);
                #pragma unroll
                for (int nt = 0; nt < 4; nt++)
                    mma_bf16(acc[mt * 4 + nt], ah,
                             bl[nt >> 1][nt & 1], bl[nt >> 1][(nt & 1) + 2]);
            }
        }
        __syncthreads();
    }

    // -------- epilogue --------
    bool fused = (epi == 4);
    int which = n0 >> 9;
    float* Cb = C;
    int ldc = N, ncol0 = n0;
    if (fused) {
        Cb = C + (size_t)which * ((size_t)MROWS * 512);
        ldc = 512;
        ncol0 = n0 & 511;
    }
    bool dosilu = (epi == 1) || (epi == 3) || (fused && which == 3);

    int r_lane = lane >> 2;
    int c_lane = (lane & 3) * 2;
    #pragma unroll
    for (int mt = 0; mt < MT; mt++) {
        int r0 = m0 + wm * (16 * MT) + mt * 16 + r_lane;
        int r1 = r0 + 8;
        #pragma unroll
        for (int nt = 0; nt < 4; nt++) {
            float* a = acc[mt * 4 + nt];
            int ncb = wn * 32 + nt * 8 + c_lane;   // 0..63 in block
            float b0 = bias[n0 + ncb], b1 = bias[n0 + ncb + 1];
            float x0 = a[0] + b0, x1 = a[1] + b1;
            float y0 = a[2] + b0, y1 = a[3] + b1;
            if (dosilu) {
                x0 = x0 / (1.f + expf(-x0));
                x1 = x1 / (1.f + expf(-x1));
                y0 = y0 / (1.f + expf(-y0));
                y1 = y1 / (1.f + expf(-y1));
            }
            int nn = ncol0 + ncb;
            if (epi == 3) {
                __nv_bfloat162 h0 = __floats2bfloat162_rn(x0, x1);
                __nv_bfloat162 h1 = __floats2bfloat162_rn(y0, y1);
                float2 f0 = __bfloat1622float2(h0);
                float2 f1 = __bfloat1622float2(h1);
                __nv_bfloat162 l0 = __floats2bfloat162_rn(x0 - f0.x, x1 - f0.y);
                __nv_bfloat162 l1 = __floats2bfloat162_rn(y0 - f1.x, y1 - f1.y);
                *(__nv_bfloat162*)(Ch + (size_t)r0 * N + nn) = h0;
                *(__nv_bfloat162*)(Cl + (size_t)r0 * N + nn) = l0;
                *(__nv_bfloat162*)(Ch + (size_t)r1 * N + nn) = h1;
                *(__nv_bfloat162*)(Cl + (size_t)r1 * N + nn) = l1;
            } else {
                float* p0 = Cb + (size_t)r0 * ldc + nn;
                float* p1 = Cb + (size_t)r1 * ldc + nn;
                if (epi == 2) {
                    float2 c0 = *(float2*)p0;
                    float2 c1 = *(float2*)p1;
                    x0 += c0.x; x1 += c0.y;
                    y0 += c1.x; y1 += c1.y;
                }
                *(float2*)p0 = make_float2(x0, x1);
                *(float2*)p1 = make_float2(y0, y1);
            }
        }
    }
}

// ======== retention phase 1 (HMMA, 512 threads: 1 MMA tile per warp) ========
__global__ void __launch_bounds__(512)
ret_phase1(const float* __restrict__ k, const float* __restrict__ v,
           float* __restrict__ chunkS)
{
    __shared__ __nv_bfloat16 kth[64 * 80], ktl[64 * 80];
    __shared__ __nv_bfloat16 vth[64 * 80], vtl[64 * 80];
    __shared__ float gpow[CHK + 1];

    int z  = blockIdx.x;
    int bh = z / NCHUNK, c = z - bh * NCHUNK;
    int b  = bh >> 3, hh = bh & 7;
    int tid = threadIdx.x;
    float gamma = 1.f - exp2f(-5.f - (float)hh);
    if (tid <= CHK) gpow[tid] = powf(gamma, (float)tid);
    __nv_bfloat16 z16 = __float2bfloat16(0.f);
    for (int t = tid; t < 64 * 12; t += 512) {
        int d = t / 12, j = 68 + (t % 12);
        int idx = d * 80 + j;
        kth[idx] = z16; ktl[idx] = z16;
        vth[idx] = z16; vtl[idx] = z16;
    }
    __syncthreads();

    int base = ((b * SS + c * CHK) * HH + hh) * DH;
    for (int i = tid; i < CHK * DH; i += 512) {
        int r = i >> 6, d = i & 63;
        int g = base + r * DD + d;
        int spos = c * CHK + r;
        int j = d & 31;
        float cs = g_rotcs[spos * 32 + j];
        float sn = g_rotsn[spos * 32 + j];
        float ka = k[g];
        float kb = (d < 32) ? -k[g + 32] : k[g - 32];
        float kv = (ka * cs + kb * sn) * 0.125f * gpow[CHK - 1 - r];
        __nv_bfloat16 h, l;
        bsplit(kv, h, l);
        kth[d * 80 + r] = h;
        ktl[d * 80 + r] = l;
        float vv = v[g];
        bsplit(vv, h, l);
        vth[d * 80 + r] = h;
        vtl[d * 80 + r] = l;
    }
    __syncthreads();

    uint32_t kthA = smem_u32(kth), ktlA = smem_u32(ktl);
    uint32_t vthA = smem_u32(vth), vtlA = smem_u32(vtl);
    int lane = tid & 31, wid = tid >> 5;   // 16 warps
    uint32_t rowoff = (uint32_t)((lane & 15) * 160 + (lane >> 4) * 16);
    float* out = chunkS + (size_t)z * (DH * DH);

    {
        int u = wid;
        int mt = u >> 2, nb = u & 3;
        float acc[2][4] = {};
        #pragma unroll
        for (int kst = 0; kst < 5; kst++) {
            uint32_t koff = (uint32_t)(kst * 32);
            uint32_t ah[4], al[4], bh4[4], bl4[4];
            ldsm4(ah, kthA + mt * (16 * 160) + rowoff + koff);
            ldsm4(al, ktlA + mt * (16 * 160) + rowoff + koff);
            ldsm4(bh4, vthA + nb * (16 * 160) + rowoff + koff);
            ldsm4(bl4, vtlA + nb * (16 * 160) + rowoff + koff);
            #pragma unroll
            for (int half = 0; half < 2; half++) {
                mma_bf16(acc[half], ah, bh4[half], bh4[half + 2]);
                mma_bf16(acc[half], al, bh4[half], bh4[half + 2]);
                mma_bf16(acc[half], ah, bl4[half], bl4[half + 2]);
            }
        }
        int r0 = mt * 16 + (lane >> 2);
        #pragma unroll
        for (int half = 0; half < 2; half++) {
            int c0 = nb * 16 + half * 8 + (lane & 3) * 2;
            out[r0 * 64 + c0]           = acc[half][0];
            out[r0 * 64 + c0 + 1]       = acc[half][1];
            out[(r0 + 8) * 64 + c0]     = acc[half][2];
            out[(r0 + 8) * 64 + c0 + 1] = acc[half][3];
        }
    }
}

// ===== retention phase 2 (FFMA overlay, 512 thr) + FUSED gnorm*gate =====
#define KT_PITCH 72
#define RET2_FLOATS (2 * CHK * DH + DH * DH + 4624)
__global__ void __launch_bounds__(512)
ret_phase2(const float* __restrict__ q, const float* __restrict__ k,
           const float* __restrict__ v, const float* __restrict__ chunkS,
           const float* __restrict__ gnw, const float* __restrict__ gnb,
           const float* __restrict__ gate,
           __nv_bfloat16* __restrict__ ghi, __nv_bfloat16* __restrict__ glo)
{
    extern __shared__ float smf[];
    float* sq    = smf;
    float* sv    = sq + CHK * DH;
    float* st    = sv + CHK * DH;
    float* skT   = st + DH * DH;
    float* inner = skT;
    __shared__ float gpow[CHK + 1];

    int z  = blockIdx.x;
    int bh = z / NCHUNK, c = z - bh * NCHUNK;
    int b  = bh >> 3, hh = bh & 7;
    int tid = threadIdx.x;
    float gamma = 1.f - exp2f(-5.f - (float)hh);
    if (tid <= CHK) gpow[tid] = powf(gamma, (float)tid);
    __syncthreads();
    float chunk_dec = gpow[CHK];

    int base = ((b * SS + c * CHK) * HH + hh) * DH;
    for (int i = tid; i < CHK * DH; i += 512) {
        int r = i >> 6, d = i & 63;
        int g = base + r * DD + d;
        int spos = c * CHK + r;
        int j = d & 31;
        float cs = g_rotcs[spos * 32 + j];
        float sn = g_rotsn[spos * 32 + j];
        float qa = q[g], ka = k[g];
        float qb, kb;
        if (d < 32) { qb = -q[g + 32]; kb = -k[g + 32]; }
        else        { qb =  q[g - 32]; kb =  k[g - 32]; }
        sq[i] = qa * cs + qb * sn;
        skT[d * KT_PITCH + r] = (ka * cs + kb * sn) * 0.125f;
        sv[i] = v[g];
    }
    {
        const float* Sbase = chunkS + (size_t)(bh * NCHUNK) * (DH * DH);
        #pragma unroll
        for (int g4 = 0; g4 < 2; g4++) {
            int idx = tid * 8 + g4 * 4;
            float4 acc = make_float4(0.f, 0.f, 0.f, 0.f);
            float w = 1.f;
            for (int cc = c - 1; cc >= 0; cc--) {
                float4 sv4 = *(const float4*)(Sbase + (size_t)cc * (DH * DH) + idx);
                acc.x += w * sv4.x; acc.y += w * sv4.y;
                acc.z += w * sv4.z; acc.w += w * sv4.w;
                w *= chunk_dec;
            }
            *(float4*)(st + idx) = acc;
        }
    }
    __syncthreads();

    float ir[3][4];
    #pragma unroll
    for (int it = 0; it < 3; it++) {
        int e = tid + it * 512;
        if (e < CHK * 17) {
            int i = e / 17, jg = e - i * 17;
            int j0 = jg * 4;
            float4 s = make_float4(0.f, 0.f, 0.f, 0.f);
            if (i >= j0) {
                const float* qi = sq + i * DH;
                #pragma unroll 4
                for (int d4 = 0; d4 < DH; d4 += 4) {
                    float4 qv = *(const float4*)(qi + d4);
                    float4 k0 = *(const float4*)(skT + (d4 + 0) * KT_PITCH + j0);
                    float4 k1 = *(const float4*)(skT + (d4 + 1) * KT_PITCH + j0);
                    float4 k2 = *(const float4*)(skT + (d4 + 2) * KT_PITCH + j0);
                    float4 k3 = *(const float4*)(skT + (d4 + 3) * KT_PITCH + j0);
                    s.x += qv.x*k0.x + qv.y*k1.x + qv.z*k2.x + qv.w*k3.x;
                    s.y += qv.x*k0.y + qv.y*k1.y + qv.z*k2.y + qv.w*k3.y;
                    s.z += qv.x*k0.z + qv.y*k1.z + qv.z*k2.z + qv.w*k3.z;
                    s.w += qv.x*k0.w + qv.y*k1.w + qv.z*k2.w + qv.w*k3.w;
                }
            }
            ir[it][0] = s.x; ir[it][1] = s.y;
            ir[it][2] = s.z; ir[it][3] = s.w;
        }
    }
    __syncthreads();
    #pragma unroll
    for (int it = 0; it < 3; it++) {
        int e = tid + it * 512;
        if (e < CHK * 17) {
            int i = e / 17, jg = e - i * 17;
            int j0 = jg * 4;
            float* out = inner + i * CHK + j0;
            out[0] = (i >= j0)     ? ir[it][0] * gpow[i - j0]     : 0.f;
            out[1] = (i >= j0 + 1) ? ir[it][1] * gpow[i - j0 - 1] : 0.f;
            out[2] = (i >= j0 + 2) ? ir[it][2] * gpow[i - j0 - 2] : 0.f;
            out[3] = (i >= j0 + 3) ? ir[it][3] * gpow[i - j0 - 3] : 0.f;
        }
    }
    __syncthreads();

    #pragma unroll
    for (int kk = 0; kk < 3; kk++) {
        int e = tid + kk * 512;
        if (e >= CHK * 16) break;
        int i = e >> 4, d4 = (e & 15) << 2;
        float4 acc = make_float4(0.f, 0.f, 0.f, 0.f);
        const float* in_i = inner + i * CHK;
        for (int j = 0; j <= i; j++) {
            float w = in_i[j];
            float4 vv = *(const float4*)(sv + j * DH + d4);
            acc.x += w * vv.x; acc.y += w * vv.y;
            acc.z += w * vv.z; acc.w += w * vv.w;
        }
        float4 a2 = make_float4(0.f, 0.f, 0.f, 0.f);
        const float* qi = sq + i * DH;
        #pragma unroll 8
        for (int ee = 0; ee < DH; ee++) {
            float qv = qi[ee];
            float4 sr = *(const float4*)(st + ee * DH + d4);
            a2.x += qv * sr.x; a2.y += qv * sr.y;
            a2.z += qv * sr.z; a2.w += qv * sr.w;
        }
        float cd = gamma * gpow[i];
        acc.x += a2.x * cd; acc.y += a2.y * cd;
        acc.z += a2.z * cd; acc.w += a2.w * cd;

        float lsum = acc.x + acc.y + acc.z + acc.w;
        float lss  = acc.x*acc.x + acc.y*acc.y + acc.z*acc.z + acc.w*acc.w;
        #pragma unroll
        for (int o = 8; o; o >>= 1) {
            lsum += __shfl_xor_sync(0xffffffffu, lsum, o);
            lss  += __shfl_xor_sync(0xffffffffu, lss,  o);
        }
        float mean = lsum * (1.f / DH);
        float var  = lss * (1.f / DH) - mean * mean;
        float rstd = rsqrtf(var + EPS);
        int wi = hh * DH + d4;
        float4 gw = *(const float4*)(gnw + wi);
        float4 gb = *(const float4*)(gnb + wi);
        int gidx = base + i * DD + d4;
        float4 gt = *(const float4*)(gate + gidx);
        float p0 = gt.x * ((acc.x - mean) * rstd * gw.x + gb.x);
        float p1 = gt.y * ((acc.y - mean) * rstd * gw.y + gb.y);
        float p2 = gt.z * ((acc.z - mean) * rstd * gw.z + gb.z);
        float p3 = gt.w * ((acc.w - mean) * rstd * gw.w + gb.w);
        __nv_bfloat162 h0 = __floats2bfloat162_rn(p0, p1);
        __nv_bfloat162 h1 = __floats2bfloat162_rn(p2, p3);
        float2 f0 = __bfloat1622float2(h0);
        float2 f1 = __bfloat1622float2(h1);
        __nv_bfloat162 l0 = __floats2bfloat162_rn(p0 - f0.x, p1 - f0.y);
        __nv_bfloat162 l1 = __floats2bfloat162_rn(p2 - f1.x, p3 - f1.y);
        *(__nv_bfloat162*)(ghi + gidx)     = h0;
        *(__nv_bfloat162*)(ghi + gidx + 2) = h1;
        *(__nv_bfloat162*)(glo + gidx)     = l0;
        *(__nv_bfloat162*)(glo + gidx + 2) = l1;
    }
}

// ---------------- host orchestration ----------------
extern "C" void kernel_launch(void* const* d_in, const int* in_sizes, int n_in,
                              void* d_out, int out_size)
{
    const int*   tokens = (const int*)  d_in[0];
    const float* emb    = (const float*)d_in[1];
    const float* Wq = (const float*)d_in[2],  * bq = (const float*)d_in[3];
    const float* Wk = (const float*)d_in[4],  * bk = (const float*)d_in[5];
    const float* Wv = (const float*)d_in[6],  * bv = (const float*)d_in[7];
    const float* Wg = (const float*)d_in[8],  * bg = (const float*)d_in[9];
    const float* Wo = (const float*)d_in[10], * bo = (const float*)d_in[11];
    const float* gnw  = (const float*)d_in[12], * gnb  = (const float*)d_in[13];
    const float* ln1w = (const float*)d_in[14], * ln1b = (const float*)d_in[15];
    const float* ln2w = (const float*)d_in[16], * ln2b = (const float*)d_in[17];
    const float* w1 = (const float*)d_in[18], * b1 = (const float*)d_in[19];
    const float* w2 = (const float*)d_in[20], * b2 = (const float*)d_in[21];

    float* x = (float*)d_out;

    float* fb = nullptr;
    cudaGetSymbolAddress((void**)&fb, g_scratch);
    const size_t SZ = (size_t)MROWS * DD;
    float* q = fb;                           // q,k,v,gate consecutive (epi4!)

    float* chunkS = nullptr;
    cudaGetSymbolAddress((void**)&chunkS, g_chunkS);

    __nv_bfloat16* ab = nullptr;
    cudaGetSymbolAddress((void**)&ab, g_act);
    __nv_bfloat16* h_hi  = ab;
    __nv_bfloat16* h_lo  = ab + SZ;
    __nv_bfloat16* g_hi  = ab + 2 * SZ;
    __nv_bfloat16* g_lo  = ab + 3 * SZ;
    __nv_bfloat16* ff_hi = ab + 4 * SZ;
    __nv_bfloat16* ff_lo = ab + 8 * SZ;

    __nv_bfloat16* wts = nullptr;
    cudaGetSymbolAddress((void**)&wts, g_wts);
    __nv_bfloat16* qkvg_h = wts;             // [L][2048][512]
    __nv_bfloat16* qkvg_l = wts + 4 * W5;
    __nv_bfloat16* wo_h   = wts + 8 * W5;
    __nv_bfloat16* wo_l   = wts + 9 * W5;
    __nv_bfloat16* w1_h   = wts + 10 * W5;
    __nv_bfloat16* w1_l   = wts + 10 * W5 + WF;
    __nv_bfloat16* w2_h   = wts + 10 * W5 + 2 * WF;
    __nv_bfloat16* w2_l   = wts + 10 * W5 + 3 * WF;

    float* biasP = nullptr;
    cudaGetSymbolAddress((void**)&biasP, g_bias);

    const int RET2_SMEM  = RET2_FLOATS * (int)sizeof(float);
    const int GEMM_SMEM2 = 2 * (2 * 128 * APITCH + 2 * 64 * APITCH);  // 110592
    const int GEMM_SMEM1 = 2 * (2 * 64 * APITCH + 2 * 64 * APITCH);   // 73728
    cudaFuncSetAttribute(ret_phase2,
                         cudaFuncAttributeMaxDynamicSharedMemorySize, RET2_SMEM);
    cudaFuncSetAttribute(tc_gemm<2>,
                         cudaFuncAttributeMaxDynamicSharedMemorySize, GEMM_SMEM2);
    cudaFuncSetAttribute(tc_gemm<1>,
                         cudaFuncAttributeMaxDynamicSharedMemorySize, GEMM_SMEM1);

    dim3 wb(32, 8);
    dim3 gemmQKVG(2048 / 64, MROWS / 128);   // (32, 51)  MT=2
    dim3 gemmO(DD / 64, MROWS / 64);         // (8, 102)  MT=1
    dim3 gemmF1(FFN / 64, MROWS / 128);      // (32, 51)  MT=2
    dim3 gemmF2(DD / 64, MROWS / 64);        // (8, 102)  MT=1
    const int NRET = BB * HH * NCHUNK;       // 768

    for (int l = 0; l < LL; l++) {
        const size_t oQW = (size_t)l * 2048 * DD;
        const size_t oW  = (size_t)l * DD * DD;
        const size_t oF  = (size_t)l * DD * FFN;
        const size_t ob  = (size_t)l * DD;
        const size_t obf = (size_t)l * FFN;

        if (l == 0) {
            wconv5_kernel<<<dim3(16, 16, 5 * LL), wb>>>(Wq, Wk, Wv, Wg, Wo,
                                                        qkvg_h, qkvg_l, wo_h, wo_l);
            embed_ln_kernel<<<MROWS, 256>>>(tokens, emb, ln1w, ln1b, x, h_hi, h_lo,
                                            bq, bk, bv, bg, biasP);
        } else {
            layernorm_split_kernel<<<MROWS, 256>>>(x, ln1w + ob, ln1b + ob, h_hi, h_lo);
        }

        tc_gemm<2><<<gemmQKVG, 256, GEMM_SMEM2>>>(h_hi, h_lo, qkvg_h + oQW, qkvg_l + oQW,
                                                  biasP + (size_t)l * 2048, q,
                                                  nullptr, nullptr, DD, 2048, 4);

        ret_phase1<<<NRET, 512>>>(q + SZ, q + 2 * SZ, chunkS);
        ret_phase2<<<NRET, 512, RET2_SMEM>>>(q, q + SZ, q + 2 * SZ, chunkS,
                                             gnw + ob, gnb + ob, q + 3 * SZ,
                                             g_hi, g_lo);

        tc_gemm<1><<<gemmO, 256, GEMM_SMEM1>>>(g_hi, g_lo, wo_h + oW, wo_l + oW,
                                               bo + ob, x, nullptr, nullptr, DD, DD, 2);

        if (l == 0) {
            wconv_kernel<<<dim3(FFN / 32, DD / 32, LL), wb>>>(w1, w1_h, w1_l, DD, FFN);
            wconv_kernel<<<dim3(DD / 32, FFN / 32, LL), wb>>>(w2, w2_h, w2_l, FFN, DD);
        }

        layernorm_split_kernel<<<MROWS, 256>>>(x, ln2w + ob, ln2b + ob, h_hi, h_lo);

        tc_gemm<2><<<gemmF1, 256, GEMM_SMEM2>>>(h_hi, h_lo, w1_h + oF, w1_l + oF,
                                                b1 + obf, nullptr, ff_hi, ff_lo,
                                                DD, FFN, 3);
        tc_gemm<1><<<gemmF2, 256, GEMM_SMEM1>>>(ff_hi, ff_lo, w2_h + oF, w2_l + oF,
                                                b2 + ob, x, nullptr, nullptr,
                                                FFN, DD, 2);
    }
}

// round 14
// speedup vs baseline: 1.0761x; 1.0151x over previous
#include <cuda_runtime.h>
#include <cuda_bf16.h>
#include <math.h>
#include <stdint.h>

// ---------------- problem constants ----------------
#define BB   16
#define SS   408
#define DD   512
#define LL   10
#define FFN  2048
#define HH   8
#define DH   64
#define CHK  68
#define NCHUNK (SS/CHK)     // 6
#define MROWS (BB*SS)       // 6528
#define EPS  1e-5f

// ---------------- scratch (no allocations allowed) ----------------
__device__ __align__(16) float g_scratch[(size_t)5 * MROWS * DD];
__device__ __align__(16) float g_chunkS[(size_t)BB * HH * NCHUNK * DH * DH];
__device__ __align__(16) __nv_bfloat16 g_act[(size_t)12 * MROWS * DD];
#define W5  ((size_t)LL * DD * DD)
#define WF  ((size_t)LL * DD * FFN)
__device__ __align__(16) __nv_bfloat16 g_wts[10 * W5 + 4 * WF];
__device__ __align__(16) float g_bias[(size_t)LL * 2048];
__device__ __align__(16) float g_rotcs[SS * 32];
__device__ __align__(16) float g_rotsn[SS * 32];

// ================= PTX helpers (family-portable: sm_80+) =================
__device__ __forceinline__ uint32_t smem_u32(const void* p) {
    uint32_t a;
    asm("{ .reg .u64 t; cvta.to.shared.u64 t, %1; cvt.u32.u64 %0, t; }"
        : "=r"(a) : "l"(p));
    return a;
}
__device__ __forceinline__ void cp16(uint32_t dst, const void* src) {
    asm volatile("cp.async.cg.shared.global [%0], [%1], 16;"
                 :: "r"(dst), "l"(src));
}
#define CP_COMMIT() asm volatile("cp.async.commit_group;" ::: "memory")
#define CP_WAIT(n)  asm volatile("cp.async.wait_group %0;" :: "n"(n) : "memory")

__device__ __forceinline__ void ldsm4(uint32_t* r, uint32_t addr) {
    asm volatile("ldmatrix.sync.aligned.m8n8.x4.shared.b16 {%0,%1,%2,%3}, [%4];"
                 : "=r"(r[0]), "=r"(r[1]), "=r"(r[2]), "=r"(r[3]) : "r"(addr));
}
__device__ __forceinline__ void mma_bf16(float* c, const uint32_t* a,
                                         uint32_t b0, uint32_t b1) {
    asm volatile(
        "mma.sync.aligned.m16n8k16.row.col.f32.bf16.bf16.f32 "
        "{%0,%1,%2,%3}, {%4,%5,%6,%7}, {%8,%9}, {%0,%1,%2,%3};"
        : "+f"(c[0]), "+f"(c[1]), "+f"(c[2]), "+f"(c[3])
        : "r"(a[0]), "r"(a[1]), "r"(a[2]), "r"(a[3]), "r"(b0), "r"(b1));
}
__device__ __forceinline__ void bsplit(float f, __nv_bfloat16& h, __nv_bfloat16& l) {
    h = __float2bfloat16(f);
    l = __float2bfloat16(f - __bfloat162float(h));
}

// ------- weight transpose + bf16 hi/lo split: 5 square mats fused -------
__global__ void wconv5_kernel(const float* __restrict__ Wq, const float* __restrict__ Wk,
                              const float* __restrict__ Wv, const float* __restrict__ Wg,
                              const float* __restrict__ Wo,
                              __nv_bfloat16* __restrict__ qkvg_h, __nv_bfloat16* __restrict__ qkvg_l,
                              __nv_bfloat16* __restrict__ wo_h,   __nv_bfloat16* __restrict__ wo_l)
{
    __shared__ float t[32][33];
    int z = blockIdx.z;
    int m = z / LL, l = z - m * LL;
    const float* S = (m == 0) ? Wq : (m == 1) ? Wk : (m == 2) ? Wv : (m == 3) ? Wg : Wo;
    const float* s = S + (size_t)l * DD * DD;
    int n0 = blockIdx.x * 32, k0 = blockIdx.y * 32;
    int tx = threadIdx.x, ty = threadIdx.y;
    #pragma unroll
    for (int r = ty; r < 32; r += 8)
        t[r][tx] = s[(size_t)(k0 + r) * DD + n0 + tx];
    __syncthreads();
    __nv_bfloat16* hi;
    __nv_bfloat16* lo;
    size_t dbase;
    if (m < 4) {
        hi = qkvg_h; lo = qkvg_l;
        dbase = (size_t)l * 2048 * DD + (size_t)m * 512 * DD;
    } else {
        hi = wo_h; lo = wo_l;
        dbase = (size_t)l * DD * DD;
    }
    #pragma unroll
    for (int r = ty; r < 32; r += 8) {
        float x = t[tx][r];
        __nv_bfloat16 h, lw;
        bsplit(x, h, lw);
        size_t o = dbase + (size_t)(n0 + r) * DD + k0 + tx;
        hi[o] = h;
        lo[o] = lw;
    }
}

// ---------------- generic weight transpose (ff mats) --------------
__global__ void wconv_kernel(const float* __restrict__ src,
                             __nv_bfloat16* __restrict__ hi,
                             __nv_bfloat16* __restrict__ lo,
                             int K, int N)
{
    __shared__ float t[32][33];
    int n0 = blockIdx.x * 32, k0 = blockIdx.y * 32;
    const float* s = src + (size_t)blockIdx.z * K * N;
    int tx = threadIdx.x, ty = threadIdx.y;
    #pragma unroll
    for (int r = ty; r < 32; r += 8)
        t[r][tx] = s[(size_t)(k0 + r) * N + n0 + tx];
    __syncthreads();
    size_t dbase = (size_t)blockIdx.z * N * K;
    #pragma unroll
    for (int r = ty; r < 32; r += 8) {
        float x = t[tx][r];
        __nv_bfloat16 h, lw;
        bsplit(x, h, lw);
        size_t o = dbase + (size_t)(n0 + r) * K + k0 + tx;
        hi[o] = h;
        lo[o] = lw;
    }
}

// ---- fused: embedding gather + LN(layer0) split + bias pack + rot tables ----
__global__ void embed_ln_kernel(const int* __restrict__ tokens,
                                const float* __restrict__ emb,
                                const float* __restrict__ w,
                                const float* __restrict__ b,
                                float* __restrict__ x,
                                __nv_bfloat16* __restrict__ hi,
                                __nv_bfloat16* __restrict__ lo,
                                const float* __restrict__ bq,
                                const float* __restrict__ bk,
                                const float* __restrict__ bv,
                                const float* __restrict__ bg,
                                float* __restrict__ biasPacked)
{
    int row = blockIdx.x;
    int tid = threadIdx.x;                 // 256
    int tok = tokens[row];
    const float* src = emb + (size_t)tok * DD;
    float v0 = src[tid], v1 = src[tid + 256];
    size_t base = (size_t)row * DD;
    x[base + tid]       = v0;
    x[base + tid + 256] = v1;

    float s = v0 + v1, ss = v0*v0 + v1*v1;
    __shared__ float rs[8], rss[8];
    #pragma unroll
    for (int o = 16; o; o >>= 1) {
        s  += __shfl_xor_sync(0xffffffffu, s,  o);
        ss += __shfl_xor_sync(0xffffffffu, ss, o);
    }
    if ((tid & 31) == 0) { rs[tid >> 5] = s; rss[tid >> 5] = ss; }
    __syncthreads();
    float tot = 0.f, tots = 0.f;
    #pragma unroll
    for (int i = 0; i < 8; i++) { tot += rs[i]; tots += rss[i]; }
    float mean = tot * (1.f / DD);
    float var  = tots * (1.f / DD) - mean * mean;
    float rstd = rsqrtf(var + EPS);
    float o0 = (v0 - mean) * rstd * w[tid]       + b[tid];
    float o1 = (v1 - mean) * rstd * w[tid + 256] + b[tid + 256];
    __nv_bfloat16 h0, l0, h1, l1;
    bsplit(o0, h0, l0);
    bsplit(o1, h1, l1);
    hi[base + tid]       = h0;
    hi[base + tid + 256] = h1;
    lo[base + tid]       = l0;
    lo[base + tid + 256] = l1;

    if (row < (LL * 2048) / 512) {
        #pragma unroll
        for (int t = 0; t < 2; t++) {
            int gi = row * 512 + tid + t * 256;
            int l = gi >> 11, r = gi & 2047;
            int wsel = r >> 9, d = r & 511;
            const float* sp = (wsel == 0) ? bq : (wsel == 1) ? bk : (wsel == 2) ? bv : bg;
            biasPacked[gi] = sp[l * 512 + d];
        }
    }
    if (row < SS && tid < 32) {
        float inv = powf(10000.f, -2.f * (float)tid / 64.f);
        float ang = (float)row * inv;
        float sn, cs;
        sincosf(ang, &sn, &cs);
        g_rotcs[row * 32 + tid] = cs;
        g_rotsn[row * 32 + tid] = sn;
    }
}

// ---- layer norm (+ optional split-K partial fold into x) -> bf16 hi/lo ----
__global__ void layernorm_split_kernel(float* __restrict__ x,
                                       const float* __restrict__ addend,
                                       const float* __restrict__ w,
                                       const float* __restrict__ b,
                                       __nv_bfloat16* __restrict__ hi,
                                       __nv_bfloat16* __restrict__ lo)
{
    int row = blockIdx.x;
    int tid = threadIdx.x;                 // 256
    size_t base = (size_t)row * DD;
    float* xr = x + base;
    float v0 = xr[tid], v1 = xr[tid + 256];
    if (addend) {
        const float* ar = addend + base;
        v0 += ar[tid];
        v1 += ar[tid + 256];
        xr[tid]       = v0;                // fold partial into residual stream
        xr[tid + 256] = v1;
    }
    float s = v0 + v1, ss = v0*v0 + v1*v1;
    __shared__ float rs[8], rss[8];
    #pragma unroll
    for (int o = 16; o; o >>= 1) {
        s  += __shfl_xor_sync(0xffffffffu, s,  o);
        ss += __shfl_xor_sync(0xffffffffu, ss, o);
    }
    if ((tid & 31) == 0) { rs[tid >> 5] = s; rss[tid >> 5] = ss; }
    __syncthreads();
    float tot = 0.f, tots = 0.f;
    #pragma unroll
    for (int i = 0; i < 8; i++) { tot += rs[i]; tots += rss[i]; }
    float mean = tot * (1.f / DD);
    float var  = tots * (1.f / DD) - mean * mean;
    float rstd = rsqrtf(var + EPS);
    float o0 = (v0 - mean) * rstd * w[tid]       + b[tid];
    float o1 = (v1 - mean) * rstd * w[tid + 256] + b[tid + 256];
    __nv_bfloat16 h0, l0, h1, l1;
    bsplit(o0, h0, l0);
    bsplit(o1, h1, l1);
    hi[base + tid]       = h0;
    hi[base + tid + 256] = h1;
    lo[base + tid]       = l0;
    lo[base + tid + 256] = l1;
}

// --- tensor-core GEMM (bf16 3-term, BM=128 BN=64 BK=64, 2 CTA/SM, R11) ---
// gridDim.z == 2 => split-K: z=0 does K-half 0 with normal epilogue,
// z=1 does K-half 1 and writes raw partial (no bias) to Cpart.
#define APITCH 144
#define SA_H 0
#define SA_L 18432
#define SB_H 36864
#define SB_L 46080
#define GSTG 55296
#define GEMM_SMEM (2 * GSTG)

__global__ void __launch_bounds__(256, 2)
tc_gemm(const __nv_bfloat16* __restrict__ Ah,
        const __nv_bfloat16* __restrict__ Al,
        const __nv_bfloat16* __restrict__ Bh,
        const __nv_bfloat16* __restrict__ Bl,
        const float* __restrict__ bias,
        float* __restrict__ C,
        __nv_bfloat16* __restrict__ Ch,
        __nv_bfloat16* __restrict__ Cl,
        float* __restrict__ Cpart,
        int K, int N, int epi)
{
    extern __shared__ char sm[];
    uint32_t sb = smem_u32(sm);
    int tid = threadIdx.x;
    int lane = tid & 31, wid = tid >> 5;
    int m0 = blockIdx.y * 128, n0 = blockIdx.x * 64;
    int wm = wid & 3, wn = wid >> 2;      // warp tile 32(M) x 32(N)

    int Keff = K, kbase = 0;
    bool partout = false;
    if (gridDim.z == 2) {
        Keff = K >> 1;
        kbase = blockIdx.z * Keff;
        partout = (blockIdx.z == 1);
    }
    int nst = Keff >> 6;                   // BK = 64

    float acc[8][4];
    #pragma unroll
    for (int i = 0; i < 8; i++)
        #pragma unroll
        for (int j = 0; j < 4; j++) acc[i][j] = 0.f;

    uint32_t rowoff = (uint32_t)((lane & 15) * APITCH + (lane >> 4) * 16);

    auto issue = [&](int s, int buf) {
        uint32_t dst = sb + buf * GSTG;
        int k0 = kbase + (s << 6);
        #pragma unroll
        for (int it = 0; it < 2; it++) {
            int c = tid + it * 256;          // A: 128 rows x 8 segs... (512 per it*2)
            int row = c >> 3, seg = c & 7;
            uint32_t doff = (uint32_t)(row * APITCH + seg * 16);
            size_t aoff = (size_t)(m0 + row) * K + k0 + seg * 8;
            cp16(dst + SA_H + doff, Ah + aoff);
            cp16(dst + SA_L + doff, Al + aoff);
        }
        #pragma unroll
        for (int it = 2; it < 4; it++) {
            int c = tid + (it - 2) * 256 + 512;  // remaining A rows
            int row = c >> 3, seg = c & 7;
            uint32_t doff = (uint32_t)(row * APITCH + seg * 16);
            size_t aoff = (size_t)(m0 + row) * K + k0 + seg * 8;
            cp16(dst + SA_H + doff, Ah + aoff);
            cp16(dst + SA_L + doff, Al + aoff);
        }
        #pragma unroll
        for (int it = 0; it < 2; it++) {
            int c = tid + it * 256;          // B: 64 rows x 8 segs
            int row = c >> 3, seg = c & 7;
            uint32_t doff = (uint32_t)(row * APITCH + seg * 16);
            size_t boff = (size_t)(n0 + row) * K + k0 + seg * 8;
            cp16(dst + SB_H + doff, Bh + boff);
            cp16(dst + SB_L + doff, Bl + boff);
        }
    };

    issue(0, 0);
    CP_COMMIT();

    for (int s = 0; s < nst; s++) {
        int buf = s & 1;
        if (s + 1 < nst) {
            issue(s + 1, buf ^ 1);
            CP_COMMIT();
            CP_WAIT(1);
        } else {
            CP_WAIT(0);
        }
        __syncthreads();

        uint32_t base  = sb + buf * GSTG;
        uint32_t abase = base + (uint32_t)(wm * 32 * APITCH) + rowoff;
        uint32_t bbase = base + SB_H + (uint32_t)(wn * 32 * APITCH) + rowoff;

        #pragma unroll
        for (int kst = 0; kst < 4; kst++) {
            uint32_t koff = (uint32_t)(kst * 32);
            uint32_t bh[2][4], bl[2][4];
            #pragma unroll
            for (int nb = 0; nb < 2; nb++) {
                ldsm4(bh[nb], bbase + nb * (16 * APITCH) + koff);
                ldsm4(bl[nb], bbase + (SB_L - SB_H) + nb * (16 * APITCH) + koff);
            }
            #pragma unroll
            for (int mt = 0; mt < 2; mt++) {
                uint32_t ah[4], al[4];
                ldsm4(ah, abase + SA_H + mt * (16 * APITCH) + koff);
                ldsm4(al, abase + SA_L + mt * (16 * APITCH) + koff);
                #pragma unroll
                for (int nt = 0; nt < 4; nt++)
                    mma_bf16(acc[mt * 4 + nt], ah,
                             bh[nt >> 1][nt & 1], bh[nt >> 1][(nt & 1) + 2]);
                #pragma unroll
                for (int nt = 0; nt < 4; nt++)
                    mma_bf16(acc[mt * 4 + nt], al,
                             bh[nt >> 1][nt & 1], bh[nt >> 1][(nt & 1) + 2]);
                #pragma unroll
                for (int nt = 0; nt < 4; nt++)
                    mma_bf16(acc[mt * 4 + nt], ah,
                             bl[nt >> 1][nt & 1], bl[nt >> 1][(nt & 1) + 2]);
            }
        }
        __syncthreads();
    }

    // -------- epilogue --------
    int r_lane = lane >> 2;
    int c_lane = (lane & 3) * 2;

    if (partout) {
        // raw partial, no bias, plain store
        #pragma unroll
        for (int mt = 0; mt < 2; mt++) {
            int r0 = m0 + wm * 32 + mt * 16 + r_lane;
            int r1 = r0 + 8;
            #pragma unroll
            for (int nt = 0; nt < 4; nt++) {
                float* a = acc[mt * 4 + nt];
                int nn = n0 + wn * 32 + nt * 8 + c_lane;
                *(float2*)(Cpart + (size_t)r0 * N + nn) = make_float2(a[0], a[1]);
                *(float2*)(Cpart + (size_t)r1 * N + nn) = make_float2(a[2], a[3]);
            }
        }
        return;
    }

    bool fused = (epi == 4);
    int which = n0 >> 9;
    float* Cb = C;
    int ldc = N, ncol0 = n0;
    if (fused) {
        Cb = C + (size_t)which * ((size_t)MROWS * 512);
        ldc = 512;
        ncol0 = n0 & 511;
    }
    bool dosilu = (epi == 1) || (epi == 3) || (fused && which == 3);

    #pragma unroll
    for (int mt = 0; mt < 2; mt++) {
        int r0 = m0 + wm * 32 + mt * 16 + r_lane;
        int r1 = r0 + 8;
        #pragma unroll
        for (int nt = 0; nt < 4; nt++) {
            float* a = acc[mt * 4 + nt];
            int ncb = wn * 32 + nt * 8 + c_lane;
            float b0 = bias[n0 + ncb], b1 = bias[n0 + ncb + 1];
            float x0 = a[0] + b0, x1 = a[1] + b1;
            float y0 = a[2] + b0, y1 = a[3] + b1;
            if (dosilu) {
                x0 = x0 / (1.f + expf(-x0));
                x1 = x1 / (1.f + expf(-x1));
                y0 = y0 / (1.f + expf(-y0));
                y1 = y1 / (1.f + expf(-y1));
            }
            int nn = ncol0 + ncb;
            if (epi == 3) {
                __nv_bfloat162 h0 = __floats2bfloat162_rn(x0, x1);
                __nv_bfloat162 h1 = __floats2bfloat162_rn(y0, y1);
                float2 f0 = __bfloat1622float2(h0);
                float2 f1 = __bfloat1622float2(h1);
                __nv_bfloat162 l0 = __floats2bfloat162_rn(x0 - f0.x, x1 - f0.y);
                __nv_bfloat162 l1 = __floats2bfloat162_rn(y0 - f1.x, y1 - f1.y);
                *(__nv_bfloat162*)(Ch + (size_t)r0 * N + nn) = h0;
                *(__nv_bfloat162*)(Cl + (size_t)r0 * N + nn) = l0;
                *(__nv_bfloat162*)(Ch + (size_t)r1 * N + nn) = h1;
                *(__nv_bfloat162*)(Cl + (size_t)r1 * N + nn) = l1;
            } else {
                float* p0 = Cb + (size_t)r0 * ldc + nn;
                float* p1 = Cb + (size_t)r1 * ldc + nn;
                if (epi == 2) {
                    float2 c0 = *(float2*)p0;
                    float2 c1 = *(float2*)p1;
                    x0 += c0.x; x1 += c0.y;
                    y0 += c1.x; y1 += c1.y;
                }
                *(float2*)p0 = make_float2(x0, x1);
                *(float2*)p1 = make_float2(y0, y1);
            }
        }
    }
}

// ======== retention phase 1 (HMMA, 512 threads: 1 MMA tile per warp) ========
__global__ void __launch_bounds__(512)
ret_phase1(const float* __restrict__ k, const float* __restrict__ v,
           float* __restrict__ chunkS)
{
    __shared__ __nv_bfloat16 kth[64 * 80], ktl[64 * 80];
    __shared__ __nv_bfloat16 vth[64 * 80], vtl[64 * 80];
    __shared__ float gpow[CHK + 1];

    int z  = blockIdx.x;
    int bh = z / NCHUNK, c = z - bh * NCHUNK;
    int b  = bh >> 3, hh = bh & 7;
    int tid = threadIdx.x;
    float gamma = 1.f - exp2f(-5.f - (float)hh);
    if (tid <= CHK) gpow[tid] = powf(gamma, (float)tid);
    __nv_bfloat16 z16 = __float2bfloat16(0.f);
    for (int t = tid; t < 64 * 12; t += 512) {
        int d = t / 12, j = 68 + (t % 12);
        int idx = d * 80 + j;
        kth[idx] = z16; ktl[idx] = z16;
        vth[idx] = z16; vtl[idx] = z16;
    }
    __syncthreads();

    int base = ((b * SS + c * CHK) * HH + hh) * DH;
    for (int i = tid; i < CHK * DH; i += 512) {
        int r = i >> 6, d = i & 63;
        int g = base + r * DD + d;
        int spos = c * CHK + r;
        int j = d & 31;
        float cs = g_rotcs[spos * 32 + j];
        float sn = g_rotsn[spos * 32 + j];
        float ka = k[g];
        float kb = (d < 32) ? -k[g + 32] : k[g - 32];
        float kv = (ka * cs + kb * sn) * 0.125f * gpow[CHK - 1 - r];
        __nv_bfloat16 h, l;
        bsplit(kv, h, l);
        kth[d * 80 + r] = h;
        ktl[d * 80 + r] = l;
        float vv = v[g];
        bsplit(vv, h, l);
        vth[d * 80 + r] = h;
        vtl[d * 80 + r] = l;
    }
    __syncthreads();

    uint32_t kthA = smem_u32(kth), ktlA = smem_u32(ktl);
    uint32_t vthA = smem_u32(vth), vtlA = smem_u32(vtl);
    int lane = tid & 31, wid = tid >> 5;   // 16 warps
    uint32_t rowoff = (uint32_t)((lane & 15) * 160 + (lane >> 4) * 16);
    float* out = chunkS + (size_t)z * (DH * DH);

    {
        int u = wid;
        int mt = u >> 2, nb = u & 3;
        float acc[2][4] = {};
        #pragma unroll
        for (int kst = 0; kst < 5; kst++) {
            uint32_t koff = (uint32_t)(kst * 32);
            uint32_t ah[4], al[4], bh4[4], bl4[4];
            ldsm4(ah, kthA + mt * (16 * 160) + rowoff + koff);
            ldsm4(al, ktlA + mt * (16 * 160) + rowoff + koff);
            ldsm4(bh4, vthA + nb * (16 * 160) + rowoff + koff);
            ldsm4(bl4, vtlA + nb * (16 * 160) + rowoff + koff);
            #pragma unroll
            for (int half = 0; half < 2; half++) {
                mma_bf16(acc[half], ah, bh4[half], bh4[half + 2]);
                mma_bf16(acc[half], al, bh4[half], bh4[half + 2]);
                mma_bf16(acc[half], ah, bl4[half], bl4[half + 2]);
            }
        }
        int r0 = mt * 16 + (lane >> 2);
        #pragma unroll
        for (int half = 0; half < 2; half++) {
            int c0 = nb * 16 + half * 8 + (lane & 3) * 2;
            out[r0 * 64 + c0]           = acc[half][0];
            out[r0 * 64 + c0 + 1]       = acc[half][1];
            out[(r0 + 8) * 64 + c0]     = acc[half][2];
            out[(r0 + 8) * 64 + c0 + 1] = acc[half][3];
        }
    }
}

// ===== retention phase 2 (FFMA overlay, 512 thr) + FUSED gnorm*gate =====
#define KT_PITCH 72
#define RET2_FLOATS (2 * CHK * DH + DH * DH + 4624)
__global__ void __launch_bounds__(512)
ret_phase2(const float* __restrict__ q, const float* __restrict__ k,
           const float* __restrict__ v, const float* __restrict__ chunkS,
           const float* __restrict__ gnw, const float* __restrict__ gnb,
           const float* __restrict__ gate,
           __nv_bfloat16* __restrict__ ghi, __nv_bfloat16* __restrict__ glo)
{
    extern __shared__ float smf[];
    float* sq    = smf;
    float* sv    = sq + CHK * DH;
    float* st    = sv + CHK * DH;
    float* skT   = st + DH * DH;
    float* inner = skT;
    __shared__ float gpow[CHK + 1];

    int z  = blockIdx.x;
    int bh = z / NCHUNK, c = z - bh * NCHUNK;
    int b  = bh >> 3, hh = bh & 7;
    int tid = threadIdx.x;
    float gamma = 1.f - exp2f(-5.f - (float)hh);
    if (tid <= CHK) gpow[tid] = powf(gamma, (float)tid);
    __syncthreads();
    float chunk_dec = gpow[CHK];

    int base = ((b * SS + c * CHK) * HH + hh) * DH;
    for (int i = tid; i < CHK * DH; i += 512) {
        int r = i >> 6, d = i & 63;
        int g = base + r * DD + d;
        int spos = c * CHK + r;
        int j = d & 31;
        float cs = g_rotcs[spos * 32 + j];
        float sn = g_rotsn[spos * 32 + j];
        float qa = q[g], ka = k[g];
        float qb, kb;
        if (d < 32) { qb = -q[g + 32]; kb = -k[g + 32]; }
        else        { qb =  q[g - 32]; kb =  k[g - 32]; }
        sq[i] = qa * cs + qb * sn;
        skT[d * KT_PITCH + r] = (ka * cs + kb * sn) * 0.125f;
        sv[i] = v[g];
    }
    {
        const float* Sbase = chunkS + (size_t)(bh * NCHUNK) * (DH * DH);
        #pragma unroll
        for (int g4 = 0; g4 < 2; g4++) {
            int idx = tid * 8 + g4 * 4;
            float4 acc = make_float4(0.f, 0.f, 0.f, 0.f);
            float w = 1.f;
            for (int cc = c - 1; cc >= 0; cc--) {
                float4 sv4 = *(const float4*)(Sbase + (size_t)cc * (DH * DH) + idx);
                acc.x += w * sv4.x; acc.y += w * sv4.y;
                acc.z += w * sv4.z; acc.w += w * sv4.w;
                w *= chunk_dec;
            }
            *(float4*)(st + idx) = acc;
        }
    }
    __syncthreads();

    float ir[3][4];
    #pragma unroll
    for (int it = 0; it < 3; it++) {
        int e = tid + it * 512;
        if (e < CHK * 17) {
            int i = e / 17, jg = e - i * 17;
            int j0 = jg * 4;
            float4 s = make_float4(0.f, 0.f, 0.f, 0.f);
            if (i >= j0) {
                const float* qi = sq + i * DH;
                #pragma unroll 4
                for (int d4 = 0; d4 < DH; d4 += 4) {
                    float4 qv = *(const float4*)(qi + d4);
                    float4 k0 = *(const float4*)(skT + (d4 + 0) * KT_PITCH + j0);
                    float4 k1 = *(const float4*)(skT + (d4 + 1) * KT_PITCH + j0);
                    float4 k2 = *(const float4*)(skT + (d4 + 2) * KT_PITCH + j0);
                    float4 k3 = *(const float4*)(skT + (d4 + 3) * KT_PITCH + j0);
                    s.x += qv.x*k0.x + qv.y*k1.x + qv.z*k2.x + qv.w*k3.x;
                    s.y += qv.x*k0.y + qv.y*k1.y + qv.z*k2.y + qv.w*k3.y;
                    s.z += qv.x*k0.z + qv.y*k1.z + qv.z*k2.z + qv.w*k3.z;
                    s.w += qv.x*k0.w + qv.y*k1.w + qv.z*k2.w + qv.w*k3.w;
                }
            }
            ir[it][0] = s.x; ir[it][1] = s.y;
            ir[it][2] = s.z; ir[it][3] = s.w;
        }
    }
    __syncthreads();
    #pragma unroll
    for (int it = 0; it < 3; it++) {
        int e = tid + it * 512;
        if (e < CHK * 17) {
            int i = e / 17, jg = e - i * 17;
            int j0 = jg * 4;
            float* out = inner + i * CHK + j0;
            out[0] = (i >= j0)     ? ir[it][0] * gpow[i - j0]     : 0.f;
            out[1] = (i >= j0 + 1) ? ir[it][1] * gpow[i - j0 - 1] : 0.f;
            out[2] = (i >= j0 + 2) ? ir[it][2] * gpow[i - j0 - 2] : 0.f;
            out[3] = (i >= j0 + 3) ? ir[it][3] * gpow[i - j0 - 3] : 0.f;
        }
    }
    __syncthreads();

    #pragma unroll
    for (int kk = 0; kk < 3; kk++) {
        int e = tid + kk * 512;
        if (e >= CHK * 16) break;
        int i = e >> 4, d4 = (e & 15) << 2;
        float4 acc = make_float4(0.f, 0.f, 0.f, 0.f);
        const float* in_i = inner + i * CHK;
        for (int j = 0; j <= i; j++) {
            float w = in_i[j];
            float4 vv = *(const float4*)(sv + j * DH + d4);
            acc.x += w * vv.x; acc.y += w * vv.y;
            acc.z += w * vv.z; acc.w += w * vv.w;
        }
        float4 a2 = make_float4(0.f, 0.f, 0.f, 0.f);
        const float* qi = sq + i * DH;
        #pragma unroll 8
        for (int ee = 0; ee < DH; ee++) {
            float qv = qi[ee];
            float4 sr = *(const float4*)(st + ee * DH + d4);
            a2.x += qv * sr.x; a2.y += qv * sr.y;
            a2.z += qv * sr.z; a2.w += qv * sr.w;
        }
        float cd = gamma * gpow[i];
        acc.x += a2.x * cd; acc.y += a2.y * cd;
        acc.z += a2.z * cd; acc.w += a2.w * cd;

        float lsum = acc.x + acc.y + acc.z + acc.w;
        float lss  = acc.x*acc.x + acc.y*acc.y + acc.z*acc.z + acc.w*acc.w;
        #pragma unroll
        for (int o = 8; o; o >>= 1) {
            lsum += __shfl_xor_sync(0xffffffffu, lsum, o);
            lss  += __shfl_xor_sync(0xffffffffu, lss,  o);
        }
        float mean = lsum * (1.f / DH);
        float var  = lss * (1.f / DH) - mean * mean;
        float rstd = rsqrtf(var + EPS);
        int wi = hh * DH + d4;
        float4 gw = *(const float4*)(gnw + wi);
        float4 gb = *(const float4*)(gnb + wi);
        int gidx = base + i * DD + d4;
        float4 gt = *(const float4*)(gate + gidx);
        float p0 = gt.x * ((acc.x - mean) * rstd * gw.x + gb.x);
        float p1 = gt.y * ((acc.y - mean) * rstd * gw.y + gb.y);
        float p2 = gt.z * ((acc.z - mean) * rstd * gw.z + gb.z);
        float p3 = gt.w * ((acc.w - mean) * rstd * gw.w + gb.w);
        __nv_bfloat162 h0 = __floats2bfloat162_rn(p0, p1);
        __nv_bfloat162 h1 = __floats2bfloat162_rn(p2, p3);
        float2 f0 = __bfloat1622float2(h0);
        float2 f1 = __bfloat1622float2(h1);
        __nv_bfloat162 l0 = __floats2bfloat162_rn(p0 - f0.x, p1 - f0.y);
        __nv_bfloat162 l1 = __floats2bfloat162_rn(p2 - f1.x, p3 - f1.y);
        *(__nv_bfloat162*)(ghi + gidx)     = h0;
        *(__nv_bfloat162*)(ghi + gidx + 2) = h1;
        *(__nv_bfloat162*)(glo + gidx)     = l0;
        *(__nv_bfloat162*)(glo + gidx + 2) = l1;
    }
}

// ---------------- host orchestration ----------------
extern "C" void kernel_launch(void* const* d_in, const int* in_sizes, int n_in,
                              void* d_out, int out_size)
{
    const int*   tokens = (const int*)  d_in[0];
    const float* emb    = (const float*)d_in[1];
    const float* Wq = (const float*)d_in[2],  * bq = (const float*)d_in[3];
    const float* Wk = (const float*)d_in[4],  * bk = (const float*)d_in[5];
    const float* Wv = (const float*)d_in[6],  * bv = (const float*)d_in[7];
    const float* Wg = (const float*)d_in[8],  * bg = (const float*)d_in[9];
    const float* Wo = (const float*)d_in[10], * bo = (const float*)d_in[11];
    const float* gnw  = (const float*)d_in[12], * gnb  = (const float*)d_in[13];
    const float* ln1w = (const float*)d_in[14], * ln1b = (const float*)d_in[15];
    const float* ln2w = (const float*)d_in[16], * ln2b = (const float*)d_in[17];
    const float* w1 = (const float*)d_in[18], * b1 = (const float*)d_in[19];
    const float* w2 = (const float*)d_in[20], * b2 = (const float*)d_in[21];

    float* x = (float*)d_out;

    float* fb = nullptr;
    cudaGetSymbolAddress((void**)&fb, g_scratch);
    const size_t SZ = (size_t)MROWS * DD;
    float* q    = fb;                        // q,k,v,gate consecutive (epi4!)
    float* part = fb + 4 * SZ;               // split-K partial buffer

    float* chunkS = nullptr;
    cudaGetSymbolAddress((void**)&chunkS, g_chunkS);

    __nv_bfloat16* ab = nullptr;
    cudaGetSymbolAddress((void**)&ab, g_act);
    __nv_bfloat16* h_hi  = ab;
    __nv_bfloat16* h_lo  = ab + SZ;
    __nv_bfloat16* g_hi  = ab + 2 * SZ;
    __nv_bfloat16* g_lo  = ab + 3 * SZ;
    __nv_bfloat16* ff_hi = ab + 4 * SZ;
    __nv_bfloat16* ff_lo = ab + 8 * SZ;

    __nv_bfloat16* wts = nullptr;
    cudaGetSymbolAddress((void**)&wts, g_wts);
    __nv_bfloat16* qkvg_h = wts;             // [L][2048][512]
    __nv_bfloat16* qkvg_l = wts + 4 * W5;
    __nv_bfloat16* wo_h   = wts + 8 * W5;
    __nv_bfloat16* wo_l   = wts + 9 * W5;
    __nv_bfloat16* w1_h   = wts + 10 * W5;
    __nv_bfloat16* w1_l   = wts + 10 * W5 + WF;
    __nv_bfloat16* w2_h   = wts + 10 * W5 + 2 * WF;
    __nv_bfloat16* w2_l   = wts + 10 * W5 + 3 * WF;

    float* biasP = nullptr;
    cudaGetSymbolAddress((void**)&biasP, g_bias);

    const int RET2_SMEM = RET2_FLOATS * (int)sizeof(float);
    cudaFuncSetAttribute(ret_phase2,
                         cudaFuncAttributeMaxDynamicSharedMemorySize, RET2_SMEM);
    cudaFuncSetAttribute(tc_gemm,
                         cudaFuncAttributeMaxDynamicSharedMemorySize, GEMM_SMEM);

    dim3 wb(32, 8);
    dim3 gemmQKVG(2048 / 64, MROWS / 128);      // (32, 51)
    dim3 gemmOsp(DD / 64, MROWS / 128, 2);      // (8, 51, 2)  split-K
    dim3 gemmF1(FFN / 64, MROWS / 128);         // (32, 51)
    dim3 gemmF2sp(DD / 64, MROWS / 128, 2);     // (8, 51, 2)  split-K
    dim3 gemmF2(DD / 64, MROWS / 128);          // (8, 51)     last layer
    const int NRET = BB * HH * NCHUNK;          // 768

    for (int l = 0; l < LL; l++) {
        const size_t oQW = (size_t)l * 2048 * DD;
        const size_t oW  = (size_t)l * DD * DD;
        const size_t oF  = (size_t)l * DD * FFN;
        const size_t ob  = (size_t)l * DD;
        const size_t obf = (size_t)l * FFN;

        if (l == 0) {
            wconv5_kernel<<<dim3(16, 16, 5 * LL), wb>>>(Wq, Wk, Wv, Wg, Wo,
                                                        qkvg_h, qkvg_l, wo_h, wo_l);
            embed_ln_kernel<<<MROWS, 256>>>(tokens, emb, ln1w, ln1b, x, h_hi, h_lo,
                                            bq, bk, bv, bg, biasP);
        } else {
            // folds previous layer's FF2 partial into x
            layernorm_split_kernel<<<MROWS, 256>>>(x, part, ln1w + ob, ln1b + ob,
                                                   h_hi, h_lo);
        }

        tc_gemm<<<gemmQKVG, 256, GEMM_SMEM>>>(h_hi, h_lo, qkvg_h + oQW, qkvg_l + oQW,
                                              biasP + (size_t)l * 2048, q,
                                              nullptr, nullptr, nullptr, DD, 2048, 4);

        ret_phase1<<<NRET, 512>>>(q + SZ, q + 2 * SZ, chunkS);
        ret_phase2<<<NRET, 512, RET2_SMEM>>>(q, q + SZ, q + 2 * SZ, chunkS,
                                             gnw + ob, gnb + ob, q + 3 * SZ,
                                             g_hi, g_lo);

        // Wo split-K: z0 -> x += (bias + half0), z1 -> part
        tc_gemm<<<gemmOsp, 256, GEMM_SMEM>>>(g_hi, g_lo, wo_h + oW, wo_l + oW,
                                             bo + ob, x, nullptr, nullptr, part,
                                             DD, DD, 2);

        if (l == 0) {
            wconv_kernel<<<dim3(FFN / 32, DD / 32, LL), wb>>>(w1, w1_h, w1_l, DD, FFN);
            wconv_kernel<<<dim3(DD / 32, FFN / 32, LL), wb>>>(w2, w2_h, w2_l, FFN, DD);
        }

        // folds Wo partial into x
        layernorm_split_kernel<<<MROWS, 256>>>(x, part, ln2w + ob, ln2b + ob,
                                               h_hi, h_lo);

        tc_gemm<<<gemmF1, 256, GEMM_SMEM>>>(h_hi, h_lo, w1_h + oF, w1_l + oF,
                                            b1 + obf, nullptr, ff_hi, ff_lo,
                                            nullptr, DD, FFN, 3);
        if (l + 1 < LL) {
            tc_gemm<<<gemmF2sp, 256, GEMM_SMEM>>>(ff_hi, ff_lo, w2_h + oF, w2_l + oF,
                                                  b2 + ob, x, nullptr, nullptr, part,
                                                  FFN, DD, 2);
        } else {
            tc_gemm<<<gemmF2, 256, GEMM_SMEM>>>(ff_hi, ff_lo, w2_h + oF, w2_l + oF,
                                                b2 + ob, x, nullptr, nullptr, nullptr,
                                                FFN, DD, 2);
        }
    }
}

// round 15
// speedup vs baseline: 1.0787x; 1.0024x over previous
#include <cuda_runtime.h>
#include <cuda_bf16.h>
#include <math.h>
#include <stdint.h>

// ---------------- problem constants ----------------
#define BB   16
#define SS   408
#define DD   512
#define LL   10
#define FFN  2048
#define HH   8
#define DH   64
#define CHK  68
#define NCHUNK (SS/CHK)     // 6
#define MROWS (BB*SS)       // 6528
#define EPS  1e-5f

// ---------------- scratch (no allocations allowed) ----------------
__device__ __align__(16) float g_scratch[(size_t)5 * MROWS * DD];
__device__ __align__(16) float g_chunkS[(size_t)BB * HH * NCHUNK * DH * DH];
__device__ __align__(16) __nv_bfloat16 g_act[(size_t)12 * MROWS * DD];
#define W5  ((size_t)LL * DD * DD)
#define WF  ((size_t)LL * DD * FFN)
__device__ __align__(16) __nv_bfloat16 g_wts[10 * W5 + 4 * WF];
__device__ __align__(16) float g_bias[(size_t)LL * 2048];
__device__ __align__(16) float g_rotcs[SS * 32];
__device__ __align__(16) float g_rotsn[SS * 32];
__device__ __align__(16) float g_gpow[HH * 72];     // gamma_h^j, j=0..68

// ================= PTX helpers (family-portable: sm_80+) =================
__device__ __forceinline__ uint32_t smem_u32(const void* p) {
    uint32_t a;
    asm("{ .reg .u64 t; cvta.to.shared.u64 t, %1; cvt.u32.u64 %0, t; }"
        : "=r"(a) : "l"(p));
    return a;
}
__device__ __forceinline__ void cp16(uint32_t dst, const void* src) {
    asm volatile("cp.async.cg.shared.global [%0], [%1], 16;"
                 :: "r"(dst), "l"(src));
}
#define CP_COMMIT() asm volatile("cp.async.commit_group;" ::: "memory")
#define CP_WAIT(n)  asm volatile("cp.async.wait_group %0;" :: "n"(n) : "memory")

__device__ __forceinline__ void ldsm4(uint32_t* r, uint32_t addr) {
    asm volatile("ldmatrix.sync.aligned.m8n8.x4.shared.b16 {%0,%1,%2,%3}, [%4];"
                 : "=r"(r[0]), "=r"(r[1]), "=r"(r[2]), "=r"(r[3]) : "r"(addr));
}
__device__ __forceinline__ void mma_bf16(float* c, const uint32_t* a,
                                         uint32_t b0, uint32_t b1) {
    asm volatile(
        "mma.sync.aligned.m16n8k16.row.col.f32.bf16.bf16.f32 "
        "{%0,%1,%2,%3}, {%4,%5,%6,%7}, {%8,%9}, {%0,%1,%2,%3};"
        : "+f"(c[0]), "+f"(c[1]), "+f"(c[2]), "+f"(c[3])
        : "r"(a[0]), "r"(a[1]), "r"(a[2]), "r"(a[3]), "r"(b0), "r"(b1));
}
__device__ __forceinline__ void bsplit(float f, __nv_bfloat16& h, __nv_bfloat16& l) {
    h = __float2bfloat16(f);
    l = __float2bfloat16(f - __bfloat162float(h));
}

// ------- weight transpose + bf16 hi/lo split: 5 square mats fused -------
__global__ void wconv5_kernel(const float* __restrict__ Wq, const float* __restrict__ Wk,
                              const float* __restrict__ Wv, const float* __restrict__ Wg,
                              const float* __restrict__ Wo,
                              __nv_bfloat16* __restrict__ qkvg_h, __nv_bfloat16* __restrict__ qkvg_l,
                              __nv_bfloat16* __restrict__ wo_h,   __nv_bfloat16* __restrict__ wo_l)
{
    __shared__ float t[32][33];
    int z = blockIdx.z;
    int m = z / LL, l = z - m * LL;
    const float* S = (m == 0) ? Wq : (m == 1) ? Wk : (m == 2) ? Wv : (m == 3) ? Wg : Wo;
    const float* s = S + (size_t)l * DD * DD;
    int n0 = blockIdx.x * 32, k0 = blockIdx.y * 32;
    int tx = threadIdx.x, ty = threadIdx.y;
    #pragma unroll
    for (int r = ty; r < 32; r += 8)
        t[r][tx] = s[(size_t)(k0 + r) * DD + n0 + tx];
    __syncthreads();
    __nv_bfloat16* hi;
    __nv_bfloat16* lo;
    size_t dbase;
    if (m < 4) {
        hi = qkvg_h; lo = qkvg_l;
        dbase = (size_t)l * 2048 * DD + (size_t)m * 512 * DD;
    } else {
        hi = wo_h; lo = wo_l;
        dbase = (size_t)l * DD * DD;
    }
    #pragma unroll
    for (int r = ty; r < 32; r += 8) {
        float x = t[tx][r];
        __nv_bfloat16 h, lw;
        bsplit(x, h, lw);
        size_t o = dbase + (size_t)(n0 + r) * DD + k0 + tx;
        hi[o] = h;
        lo[o] = lw;
    }
}

// ---------------- generic weight transpose (ff mats) --------------
__global__ void wconv_kernel(const float* __restrict__ src,
                             __nv_bfloat16* __restrict__ hi,
                             __nv_bfloat16* __restrict__ lo,
                             int K, int N)
{
    __shared__ float t[32][33];
    int n0 = blockIdx.x * 32, k0 = blockIdx.y * 32;
    const float* s = src + (size_t)blockIdx.z * K * N;
    int tx = threadIdx.x, ty = threadIdx.y;
    #pragma unroll
    for (int r = ty; r < 32; r += 8)
        t[r][tx] = s[(size_t)(k0 + r) * N + n0 + tx];
    __syncthreads();
    size_t dbase = (size_t)blockIdx.z * N * K;
    #pragma unroll
    for (int r = ty; r < 32; r += 8) {
        float x = t[tx][r];
        __nv_bfloat16 h, lw;
        bsplit(x, h, lw);
        size_t o = dbase + (size_t)(n0 + r) * K + k0 + tx;
        hi[o] = h;
        lo[o] = lw;
    }
}

// ---- fused: embed + LN(l0) split + bias pack + rot tables + gpow table ----
__global__ void embed_ln_kernel(const int* __restrict__ tokens,
                                const float* __restrict__ emb,
                                const float* __restrict__ w,
                                const float* __restrict__ b,
                                float* __restrict__ x,
                                __nv_bfloat16* __restrict__ hi,
                                __nv_bfloat16* __restrict__ lo,
                                const float* __restrict__ bq,
                                const float* __restrict__ bk,
                                const float* __restrict__ bv,
                                const float* __restrict__ bg,
                                float* __restrict__ biasPacked)
{
    int row = blockIdx.x;
    int tid = threadIdx.x;                 // 256
    int tok = tokens[row];
    const float* src = emb + (size_t)tok * DD;
    float v0 = src[tid], v1 = src[tid + 256];
    size_t base = (size_t)row * DD;
    x[base + tid]       = v0;
    x[base + tid + 256] = v1;

    float s = v0 + v1, ss = v0*v0 + v1*v1;
    __shared__ float rs[8], rss[8];
    #pragma unroll
    for (int o = 16; o; o >>= 1) {
        s  += __shfl_xor_sync(0xffffffffu, s,  o);
        ss += __shfl_xor_sync(0xffffffffu, ss, o);
    }
    if ((tid & 31) == 0) { rs[tid >> 5] = s; rss[tid >> 5] = ss; }
    __syncthreads();
    float tot = 0.f, tots = 0.f;
    #pragma unroll
    for (int i = 0; i < 8; i++) { tot += rs[i]; tots += rss[i]; }
    float mean = tot * (1.f / DD);
    float var  = tots * (1.f / DD) - mean * mean;
    float rstd = rsqrtf(var + EPS);
    float o0 = (v0 - mean) * rstd * w[tid]       + b[tid];
    float o1 = (v1 - mean) * rstd * w[tid + 256] + b[tid + 256];
    __nv_bfloat16 h0, l0, h1, l1;
    bsplit(o0, h0, l0);
    bsplit(o1, h1, l1);
    hi[base + tid]       = h0;
    hi[base + tid + 256] = h1;
    lo[base + tid]       = l0;
    lo[base + tid + 256] = l1;

    if (row < (LL * 2048) / 512) {
        #pragma unroll
        for (int t = 0; t < 2; t++) {
            int gi = row * 512 + tid + t * 256;
            int l = gi >> 11, r = gi & 2047;
            int wsel = r >> 9, d = r & 511;
            const float* sp = (wsel == 0) ? bq : (wsel == 1) ? bk : (wsel == 2) ? bv : bg;
            biasPacked[gi] = sp[l * 512 + d];
        }
    }
    if (row < SS && tid < 32) {
        float inv = powf(10000.f, -2.f * (float)tid / 64.f);
        float ang = (float)row * inv;
        float sn, cs;
        sincosf(ang, &sn, &cs);
        g_rotcs[row * 32 + tid] = cs;
        g_rotsn[row * 32 + tid] = sn;
    }
    if (row == 0 && tid < HH) {
        float gamma = 1.f - exp2f(-5.f - (float)tid);
        float wv = 1.f;
        for (int j = 0; j <= CHK; j++) {
            g_gpow[tid * 72 + j] = wv;
            wv *= gamma;
        }
    }
}

// ---- layer norm (+ optional split-K partial fold into x) -> bf16 hi/lo ----
__global__ void layernorm_split_kernel(float* __restrict__ x,
                                       const float* __restrict__ addend,
                                       const float* __restrict__ w,
                                       const float* __restrict__ b,
                                       __nv_bfloat16* __restrict__ hi,
                                       __nv_bfloat16* __restrict__ lo)
{
    int row = blockIdx.x;
    int tid = threadIdx.x;                 // 256
    size_t base = (size_t)row * DD;
    float* xr = x + base;
    float v0 = xr[tid], v1 = xr[tid + 256];
    if (addend) {
        const float* ar = addend + base;
        v0 += ar[tid];
        v1 += ar[tid + 256];
        xr[tid]       = v0;
        xr[tid + 256] = v1;
    }
    float s = v0 + v1, ss = v0*v0 + v1*v1;
    __shared__ float rs[8], rss[8];
    #pragma unroll
    for (int o = 16; o; o >>= 1) {
        s  += __shfl_xor_sync(0xffffffffu, s,  o);
        ss += __shfl_xor_sync(0xffffffffu, ss, o);
    }
    if ((tid & 31) == 0) { rs[tid >> 5] = s; rss[tid >> 5] = ss; }
    __syncthreads();
    float tot = 0.f, tots = 0.f;
    #pragma unroll
    for (int i = 0; i < 8; i++) { tot += rs[i]; tots += rss[i]; }
    float mean = tot * (1.f / DD);
    float var  = tots * (1.f / DD) - mean * mean;
    float rstd = rsqrtf(var + EPS);
    float o0 = (v0 - mean) * rstd * w[tid]       + b[tid];
    float o1 = (v1 - mean) * rstd * w[tid + 256] + b[tid + 256];
    __nv_bfloat16 h0, l0, h1, l1;
    bsplit(o0, h0, l0);
    bsplit(o1, h1, l1);
    hi[base + tid]       = h0;
    hi[base + tid + 256] = h1;
    lo[base + tid]       = l0;
    lo[base + tid + 256] = l1;
}

// --- tensor-core GEMM (bf16 3-term, BM=128 BN=64 BK=64, 2 CTA/SM, R11) ---
// gridDim.z == 2 => split-K: z=0 K-half 0 normal epilogue, z=1 raw partial.
#define APITCH 144
#define SA_H 0
#define SA_L 18432
#define SB_H 36864
#define SB_L 46080
#define GSTG 55296
#define GEMM_SMEM (2 * GSTG)

__global__ void __launch_bounds__(256, 2)
tc_gemm(const __nv_bfloat16* __restrict__ Ah,
        const __nv_bfloat16* __restrict__ Al,
        const __nv_bfloat16* __restrict__ Bh,
        const __nv_bfloat16* __restrict__ Bl,
        const float* __restrict__ bias,
        float* __restrict__ C,
        __nv_bfloat16* __restrict__ Ch,
        __nv_bfloat16* __restrict__ Cl,
        float* __restrict__ Cpart,
        int K, int N, int epi)
{
    extern __shared__ char sm[];
    uint32_t sb = smem_u32(sm);
    int tid = threadIdx.x;
    int lane = tid & 31, wid = tid >> 5;
    int m0 = blockIdx.y * 128, n0 = blockIdx.x * 64;
    int wm = wid & 3, wn = wid >> 2;      // warp tile 32(M) x 32(N)

    int Keff = K, kbase = 0;
    bool partout = false;
    if (gridDim.z == 2) {
        Keff = K >> 1;
        kbase = blockIdx.z * Keff;
        partout = (blockIdx.z == 1);
    }
    int nst = Keff >> 6;                   // BK = 64

    float acc[8][4];
    #pragma unroll
    for (int i = 0; i < 8; i++)
        #pragma unroll
        for (int j = 0; j < 4; j++) acc[i][j] = 0.f;

    uint32_t rowoff = (uint32_t)((lane & 15) * APITCH + (lane >> 4) * 16);

    auto issue = [&](int s, int buf) {
        uint32_t dst = sb + buf * GSTG;
        int k0 = kbase + (s << 6);
        #pragma unroll
        for (int it = 0; it < 4; it++) {
            int c = tid + it * 256;          // A: 128 rows x 8 segs
            int row = c >> 3, seg = c & 7;
            uint32_t doff = (uint32_t)(row * APITCH + seg * 16);
            size_t aoff = (size_t)(m0 + row) * K + k0 + seg * 8;
            cp16(dst + SA_H + doff, Ah + aoff);
            cp16(dst + SA_L + doff, Al + aoff);
        }
        #pragma unroll
        for (int it = 0; it < 2; it++) {
            int c = tid + it * 256;          // B: 64 rows x 8 segs
            int row = c >> 3, seg = c & 7;
            uint32_t doff = (uint32_t)(row * APITCH + seg * 16);
            size_t boff = (size_t)(n0 + row) * K + k0 + seg * 8;
            cp16(dst + SB_H + doff, Bh + boff);
            cp16(dst + SB_L + doff, Bl + boff);
        }
    };

    issue(0, 0);
    CP_COMMIT();

    for (int s = 0; s < nst; s++) {
        int buf = s & 1;
        if (s + 1 < nst) {
            issue(s + 1, buf ^ 1);
            CP_COMMIT();
            CP_WAIT(1);
        } else {
            CP_WAIT(0);
        }
        __syncthreads();

        uint32_t base  = sb + buf * GSTG;
        uint32_t abase = base + (uint32_t)(wm * 32 * APITCH) + rowoff;
        uint32_t bbase = base + SB_H + (uint32_t)(wn * 32 * APITCH) + rowoff;

        #pragma unroll
        for (int kst = 0; kst < 4; kst++) {
            uint32_t koff = (uint32_t)(kst * 32);
            uint32_t bh[2][4], bl[2][4];
            #pragma unroll
            for (int nb = 0; nb < 2; nb++) {
                ldsm4(bh[nb], bbase + nb * (16 * APITCH) + koff);
                ldsm4(bl[nb], bbase + (SB_L - SB_H) + nb * (16 * APITCH) + koff);
            }
            #pragma unroll
            for (int mt = 0; mt < 2; mt++) {
                uint32_t ah[4], al[4];
                ldsm4(ah, abase + SA_H + mt * (16 * APITCH) + koff);
                ldsm4(al, abase + SA_L + mt * (16 * APITCH) + koff);
                #pragma unroll
                for (int nt = 0; nt < 4; nt++)
                    mma_bf16(acc[mt * 4 + nt], ah,
                             bh[nt >> 1][nt & 1], bh[nt >> 1][(nt & 1) + 2]);
                #pragma unroll
                for (int nt = 0; nt < 4; nt++)
                    mma_bf16(acc[mt * 4 + nt], al,
                             bh[nt >> 1][nt & 1], bh[nt >> 1][(nt & 1) + 2]);
                #pragma unroll
                for (int nt = 0; nt < 4; nt++)
                    mma_bf16(acc[mt * 4 + nt], ah,
                             bl[nt >> 1][nt & 1], bl[nt >> 1][(nt & 1) + 2]);
            }
        }
        __syncthreads();
    }

    // -------- epilogue --------
    int r_lane = lane >> 2;
    int c_lane = (lane & 3) * 2;

    if (partout) {
        #pragma unroll
        for (int mt = 0; mt < 2; mt++) {
            int r0 = m0 + wm * 32 + mt * 16 + r_lane;
            int r1 = r0 + 8;
            #pragma unroll
            for (int nt = 0; nt < 4; nt++) {
                float* a = acc[mt * 4 + nt];
                int nn = n0 + wn * 32 + nt * 8 + c_lane;
                *(float2*)(Cpart + (size_t)r0 * N + nn) = make_float2(a[0], a[1]);
                *(float2*)(Cpart + (size_t)r1 * N + nn) = make_float2(a[2], a[3]);
            }
        }
        return;
    }

    bool fused = (epi == 4);
    int which = n0 >> 9;
    float* Cb = C;
    int ldc = N, ncol0 = n0;
    if (fused) {
        Cb = C + (size_t)which * ((size_t)MROWS * 512);
        ldc = 512;
        ncol0 = n0 & 511;
    }
    bool dosilu = (epi == 1) || (epi == 3) || (fused && which == 3);

    #pragma unroll
    for (int mt = 0; mt < 2; mt++) {
        int r0 = m0 + wm * 32 + mt * 16 + r_lane;
        int r1 = r0 + 8;
        #pragma unroll
        for (int nt = 0; nt < 4; nt++) {
            float* a = acc[mt * 4 + nt];
            int ncb = wn * 32 + nt * 8 + c_lane;
            float b0 = bias[n0 + ncb], b1 = bias[n0 + ncb + 1];
            float x0 = a[0] + b0, x1 = a[1] + b1;
            float y0 = a[2] + b0, y1 = a[3] + b1;
            if (dosilu) {
                x0 = x0 / (1.f + expf(-x0));
                x1 = x1 / (1.f + expf(-x1));
                y0 = y0 / (1.f + expf(-y0));
                y1 = y1 / (1.f + expf(-y1));
            }
            int nn = ncol0 + ncb;
            if (epi == 3) {
                __nv_bfloat162 h0 = __floats2bfloat162_rn(x0, x1);
                __nv_bfloat162 h1 = __floats2bfloat162_rn(y0, y1);
                float2 f0 = __bfloat1622float2(h0);
                float2 f1 = __bfloat1622float2(h1);
                __nv_bfloat162 l0 = __floats2bfloat162_rn(x0 - f0.x, x1 - f0.y);
                __nv_bfloat162 l1 = __floats2bfloat162_rn(y0 - f1.x, y1 - f1.y);
                *(__nv_bfloat162*)(Ch + (size_t)r0 * N + nn) = h0;
                *(__nv_bfloat162*)(Cl + (size_t)r0 * N + nn) = l0;
                *(__nv_bfloat162*)(Ch + (size_t)r1 * N + nn) = h1;
                *(__nv_bfloat162*)(Cl + (size_t)r1 * N + nn) = l1;
            } else {
                float* p0 = Cb + (size_t)r0 * ldc + nn;
                float* p1 = Cb + (size_t)r1 * ldc + nn;
                if (epi == 2) {
                    float2 c0 = *(float2*)p0;
                    float2 c1 = *(float2*)p1;
                    x0 += c0.x; x1 += c0.y;
                    y0 += c1.x; y1 += c1.y;
                }
                *(float2*)p0 = make_float2(x0, x1);
                *(float2*)p1 = make_float2(y0, y1);
            }
        }
    }
}

// ======== retention phase 1 (HMMA, 512 threads, unrolled gather) ========
__global__ void __launch_bounds__(512)
ret_phase1(const float* __restrict__ k, const float* __restrict__ v,
           float* __restrict__ chunkS)
{
    __shared__ __nv_bfloat16 kth[64 * 80], ktl[64 * 80];
    __shared__ __nv_bfloat16 vth[64 * 80], vtl[64 * 80];
    __shared__ float gpow[CHK + 1];

    int z  = blockIdx.x;
    int bh = z / NCHUNK, c = z - bh * NCHUNK;
    int b  = bh >> 3, hh = bh & 7;
    int tid = threadIdx.x;
    if (tid <= CHK) gpow[tid] = g_gpow[hh * 72 + tid];
    __nv_bfloat16 z16 = __float2bfloat16(0.f);
    #pragma unroll
    for (int it = 0; it < 2; it++) {
        int t = tid + it * 512;
        if (t < 64 * 12) {
            int d = t / 12, j = 68 + (t % 12);
            int idx = d * 80 + j;
            kth[idx] = z16; ktl[idx] = z16;
            vth[idx] = z16; vtl[idx] = z16;
        }
    }
    __syncthreads();

    int base = ((b * SS + c * CHK) * HH + hh) * DH;
    #pragma unroll
    for (int it = 0; it < 9; it++) {
        int i = tid + it * 512;
        if (i < CHK * DH) {
            int r = i >> 6, d = i & 63;
            int g = base + r * DD + d;
            int spos = c * CHK + r;
            int j = d & 31;
            float cs = g_rotcs[spos * 32 + j];
            float sn = g_rotsn[spos * 32 + j];
            float ka = k[g];
            float kb = (d < 32) ? -k[g + 32] : k[g - 32];
            float kv = (ka * cs + kb * sn) * 0.125f * gpow[CHK - 1 - r];
            __nv_bfloat16 h, l;
            bsplit(kv, h, l);
            kth[d * 80 + r] = h;
            ktl[d * 80 + r] = l;
            float vv = v[g];
            bsplit(vv, h, l);
            vth[d * 80 + r] = h;
            vtl[d * 80 + r] = l;
        }
    }
    __syncthreads();

    uint32_t kthA = smem_u32(kth), ktlA = smem_u32(ktl);
    uint32_t vthA = smem_u32(vth), vtlA = smem_u32(vtl);
    int lane = tid & 31, wid = tid >> 5;   // 16 warps
    uint32_t rowoff = (uint32_t)((lane & 15) * 160 + (lane >> 4) * 16);
    float* out = chunkS + (size_t)z * (DH * DH);

    {
        int u = wid;
        int mt = u >> 2, nb = u & 3;
        float acc[2][4] = {};
        #pragma unroll
        for (int kst = 0; kst < 5; kst++) {
            uint32_t koff = (uint32_t)(kst * 32);
            uint32_t ah[4], al[4], bh4[4], bl4[4];
            ldsm4(ah, kthA + mt * (16 * 160) + rowoff + koff);
            ldsm4(al, ktlA + mt * (16 * 160) + rowoff + koff);
            ldsm4(bh4, vthA + nb * (16 * 160) + rowoff + koff);
            ldsm4(bl4, vtlA + nb * (16 * 160) + rowoff + koff);
            #pragma unroll
            for (int half = 0; half < 2; half++) {
                mma_bf16(acc[half], ah, bh4[half], bh4[half + 2]);
                mma_bf16(acc[half], al, bh4[half], bh4[half + 2]);
                mma_bf16(acc[half], ah, bl4[half], bl4[half + 2]);
            }
        }
        int r0 = mt * 16 + (lane >> 2);
        #pragma unroll
        for (int half = 0; half < 2; half++) {
            int c0 = nb * 16 + half * 8 + (lane & 3) * 2;
            out[r0 * 64 + c0]           = acc[half][0];
            out[r0 * 64 + c0 + 1]       = acc[half][1];
            out[(r0 + 8) * 64 + c0]     = acc[half][2];
            out[(r0 + 8) * 64 + c0 + 1] = acc[half][3];
        }
    }
}

// ===== retention phase 2 (FFMA overlay, 512 thr) + FUSED gnorm*gate =====
#define KT_PITCH 72
#define RET2_FLOATS (2 * CHK * DH + DH * DH + 4624)
__global__ void __launch_bounds__(512)
ret_phase2(const float* __restrict__ q, const float* __restrict__ k,
           const float* __restrict__ v, const float* __restrict__ chunkS,
           const float* __restrict__ gnw, const float* __restrict__ gnb,
           const float* __restrict__ gate,
           __nv_bfloat16* __restrict__ ghi, __nv_bfloat16* __restrict__ glo)
{
    extern __shared__ float smf[];
    float* sq    = smf;
    float* sv    = sq + CHK * DH;
    float* st    = sv + CHK * DH;
    float* skT   = st + DH * DH;
    float* inner = skT;
    __shared__ float gpow[CHK + 1];

    int z  = blockIdx.x;
    int bh = z / NCHUNK, c = z - bh * NCHUNK;
    int b  = bh >> 3, hh = bh & 7;
    int tid = threadIdx.x;
    if (tid <= CHK) gpow[tid] = g_gpow[hh * 72 + tid];
    __syncthreads();
    float gamma = gpow[1];
    float chunk_dec = gpow[CHK];

    int base = ((b * SS + c * CHK) * HH + hh) * DH;
    #pragma unroll
    for (int it = 0; it < 9; it++) {
        int i = tid + it * 512;
        if (i < CHK * DH) {
            int r = i >> 6, d = i & 63;
            int g = base + r * DD + d;
            int spos = c * CHK + r;
            int j = d & 31;
            float cs = g_rotcs[spos * 32 + j];
            float sn = g_rotsn[spos * 32 + j];
            float qa = q[g], ka = k[g];
            float qb, kb;
            if (d < 32) { qb = -q[g + 32]; kb = -k[g + 32]; }
            else        { qb =  q[g - 32]; kb =  k[g - 32]; }
            sq[i] = qa * cs + qb * sn;
            skT[d * KT_PITCH + r] = (ka * cs + kb * sn) * 0.125f;
            sv[i] = v[g];
        }
    }
    {
        const float* Sbase = chunkS + (size_t)(bh * NCHUNK) * (DH * DH);
        #pragma unroll
        for (int g4 = 0; g4 < 2; g4++) {
            int idx = tid * 8 + g4 * 4;
            float4 acc = make_float4(0.f, 0.f, 0.f, 0.f);
            float w = 1.f;
            for (int cc = c - 1; cc >= 0; cc--) {
                float4 sv4 = *(const float4*)(Sbase + (size_t)cc * (DH * DH) + idx);
                acc.x += w * sv4.x; acc.y += w * sv4.y;
                acc.z += w * sv4.z; acc.w += w * sv4.w;
                w *= chunk_dec;
            }
            *(float4*)(st + idx) = acc;
        }
    }
    __syncthreads();

    float ir[3][4];
    #pragma unroll
    for (int it = 0; it < 3; it++) {
        int e = tid + it * 512;
        if (e < CHK * 17) {
            int i = e / 17, jg = e - i * 17;
            int j0 = jg * 4;
            float4 s = make_float4(0.f, 0.f, 0.f, 0.f);
            if (i >= j0) {
                const float* qi = sq + i * DH;
                #pragma unroll 4
                for (int d4 = 0; d4 < DH; d4 += 4) {
                    float4 qv = *(const float4*)(qi + d4);
                    float4 k0 = *(const float4*)(skT + (d4 + 0) * KT_PITCH + j0);
                    float4 k1 = *(const float4*)(skT + (d4 + 1) * KT_PITCH + j0);
                    float4 k2 = *(const float4*)(skT + (d4 + 2) * KT_PITCH + j0);
                    float4 k3 = *(const float4*)(skT + (d4 + 3) * KT_PITCH + j0);
                    s.x += qv.x*k0.x + qv.y*k1.x + qv.z*k2.x + qv.w*k3.x;
                    s.y += qv.x*k0.y + qv.y*k1.y + qv.z*k2.y + qv.w*k3.y;
                    s.z += qv.x*k0.z + qv.y*k1.z + qv.z*k2.z + qv.w*k3.z;
                    s.w += qv.x*k0.w + qv.y*k1.w + qv.z*k2.w + qv.w*k3.w;
                }
            }
            ir[it][0] = s.x; ir[it][1] = s.y;
            ir[it][2] = s.z; ir[it][3] = s.w;
        }
    }
    __syncthreads();
    #pragma unroll
    for (int it = 0; it < 3; it++) {
        int e = tid + it * 512;
        if (e < CHK * 17) {
            int i = e / 17, jg = e - i * 17;
            int j0 = jg * 4;
            float* out = inner + i * CHK + j0;
            out[0] = (i >= j0)     ? ir[it][0] * gpow[i - j0]     : 0.f;
            out[1] = (i >= j0 + 1) ? ir[it][1] * gpow[i - j0 - 1] : 0.f;
            out[2] = (i >= j0 + 2) ? ir[it][2] * gpow[i - j0 - 2] : 0.f;
            out[3] = (i >= j0 + 3) ? ir[it][3] * gpow[i - j0 - 3] : 0.f;
        }
    }
    __syncthreads();

    #pragma unroll
    for (int kk = 0; kk < 3; kk++) {
        int e = tid + kk * 512;
        if (e >= CHK * 16) break;
        int i = e >> 4, d4 = (e & 15) << 2;
        float4 acc = make_float4(0.f, 0.f, 0.f, 0.f);
        const float* in_i = inner + i * CHK;
        for (int j = 0; j <= i; j++) {
            float w = in_i[j];
            float4 vv = *(const float4*)(sv + j * DH + d4);
            acc.x += w * vv.x; acc.y += w * vv.y;
            acc.z += w * vv.z; acc.w += w * vv.w;
        }
        float4 a2 = make_float4(0.f, 0.f, 0.f, 0.f);
        const float* qi = sq + i * DH;
        #pragma unroll 8
        for (int ee = 0; ee < DH; ee++) {
            float qv = qi[ee];
            float4 sr = *(const float4*)(st + ee * DH + d4);
            a2.x += qv * sr.x; a2.y += qv * sr.y;
            a2.z += qv * sr.z; a2.w += qv * sr.w;
        }
        float cd = gamma * gpow[i];
        acc.x += a2.x * cd; acc.y += a2.y * cd;
        acc.z += a2.z * cd; acc.w += a2.w * cd;

        float lsum = acc.x + acc.y + acc.z + acc.w;
        float lss  = acc.x*acc.x + acc.y*acc.y + acc.z*acc.z + acc.w*acc.w;
        #pragma unroll
        for (int o = 8; o; o >>= 1) {
            lsum += __shfl_xor_sync(0xffffffffu, lsum, o);
            lss  += __shfl_xor_sync(0xffffffffu, lss,  o);
        }
        float mean = lsum * (1.f / DH);
        float var  = lss * (1.f / DH) - mean * mean;
        float rstd = rsqrtf(var + EPS);
        int wi = hh * DH + d4;
        float4 gw = *(const float4*)(gnw + wi);
        float4 gb = *(const float4*)(gnb + wi);
        int gidx = base + i * DD + d4;
        float4 gt = *(const float4*)(gate + gidx);
        float p0 = gt.x * ((acc.x - mean) * rstd * gw.x + gb.x);
        float p1 = gt.y * ((acc.y - mean) * rstd * gw.y + gb.y);
        float p2 = gt.z * ((acc.z - mean) * rstd * gw.z + gb.z);
        float p3 = gt.w * ((acc.w - mean) * rstd * gw.w + gb.w);
        __nv_bfloat162 h0 = __floats2bfloat162_rn(p0, p1);
        __nv_bfloat162 h1 = __floats2bfloat162_rn(p2, p3);
        float2 f0 = __bfloat1622float2(h0);
        float2 f1 = __bfloat1622float2(h1);
        __nv_bfloat162 l0 = __floats2bfloat162_rn(p0 - f0.x, p1 - f0.y);
        __nv_bfloat162 l1 = __floats2bfloat162_rn(p2 - f1.x, p3 - f1.y);
        *(__nv_bfloat162*)(ghi + gidx)     = h0;
        *(__nv_bfloat162*)(ghi + gidx + 2) = h1;
        *(__nv_bfloat162*)(glo + gidx)     = l0;
        *(__nv_bfloat162*)(glo + gidx + 2) = l1;
    }
}

// ---------------- host orchestration ----------------
extern "C" void kernel_launch(void* const* d_in, const int* in_sizes, int n_in,
                              void* d_out, int out_size)
{
    const int*   tokens = (const int*)  d_in[0];
    const float* emb    = (const float*)d_in[1];
    const float* Wq = (const float*)d_in[2],  * bq = (const float*)d_in[3];
    const float* Wk = (const float*)d_in[4],  * bk = (const float*)d_in[5];
    const float* Wv = (const float*)d_in[6],  * bv = (const float*)d_in[7];
    const float* Wg = (const float*)d_in[8],  * bg = (const float*)d_in[9];
    const float* Wo = (const float*)d_in[10], * bo = (const float*)d_in[11];
    const float* gnw  = (const float*)d_in[12], * gnb  = (const float*)d_in[13];
    const float* ln1w = (const float*)d_in[14], * ln1b = (const float*)d_in[15];
    const float* ln2w = (const float*)d_in[16], * ln2b = (const float*)d_in[17];
    const float* w1 = (const float*)d_in[18], * b1 = (const float*)d_in[19];
    const float* w2 = (const float*)d_in[20], * b2 = (const float*)d_in[21];

    float* x = (float*)d_out;

    float* fb = nullptr;
    cudaGetSymbolAddress((void**)&fb, g_scratch);
    const size_t SZ = (size_t)MROWS * DD;
    float* q    = fb;                        // q,k,v,gate consecutive (epi4!)
    float* part = fb + 4 * SZ;               // split-K partial buffer

    float* chunkS = nullptr;
    cudaGetSymbolAddress((void**)&chunkS, g_chunkS);

    __nv_bfloat16* ab = nullptr;
    cudaGetSymbolAddress((void**)&ab, g_act);
    __nv_bfloat16* h_hi  = ab;
    __nv_bfloat16* h_lo  = ab + SZ;
    __nv_bfloat16* g_hi  = ab + 2 * SZ;
    __nv_bfloat16* g_lo  = ab + 3 * SZ;
    __nv_bfloat16* ff_hi = ab + 4 * SZ;
    __nv_bfloat16* ff_lo = ab + 8 * SZ;

    __nv_bfloat16* wts = nullptr;
    cudaGetSymbolAddress((void**)&wts, g_wts);
    __nv_bfloat16* qkvg_h = wts;             // [L][2048][512]
    __nv_bfloat16* qkvg_l = wts + 4 * W5;
    __nv_bfloat16* wo_h   = wts + 8 * W5;
    __nv_bfloat16* wo_l   = wts + 9 * W5;
    __nv_bfloat16* w1_h   = wts + 10 * W5;
    __nv_bfloat16* w1_l   = wts + 10 * W5 + WF;
    __nv_bfloat16* w2_h   = wts + 10 * W5 + 2 * WF;
    __nv_bfloat16* w2_l   = wts + 10 * W5 + 3 * WF;

    float* biasP = nullptr;
    cudaGetSymbolAddress((void**)&biasP, g_bias);

    const int RET2_SMEM = RET2_FLOATS * (int)sizeof(float);
    cudaFuncSetAttribute(ret_phase2,
                         cudaFuncAttributeMaxDynamicSharedMemorySize, RET2_SMEM);
    cudaFuncSetAttribute(tc_gemm,
                         cudaFuncAttributeMaxDynamicSharedMemorySize, GEMM_SMEM);

    dim3 wb(32, 8);
    dim3 gemmQKVG(2048 / 64, MROWS / 128);      // (32, 51)
    dim3 gemmOsp(DD / 64, MROWS / 128, 2);      // (8, 51, 2)  split-K
    dim3 gemmF1(FFN / 64, MROWS / 128);         // (32, 51)
    dim3 gemmF2sp(DD / 64, MROWS / 128, 2);     // (8, 51, 2)  split-K
    dim3 gemmF2(DD / 64, MROWS / 128);          // (8, 51)     last layer
    const int NRET = BB * HH * NCHUNK;          // 768

    for (int l = 0; l < LL; l++) {
        const size_t oQW = (size_t)l * 2048 * DD;
        const size_t oW  = (size_t)l * DD * DD;
        const size_t oF  = (size_t)l * DD * FFN;
        const size_t ob  = (size_t)l * DD;
        const size_t obf = (size_t)l * FFN;

        if (l == 0) {
            wconv5_kernel<<<dim3(16, 16, 5 * LL), wb>>>(Wq, Wk, Wv, Wg, Wo,
                                                        qkvg_h, qkvg_l, wo_h, wo_l);
            embed_ln_kernel<<<MROWS, 256>>>(tokens, emb, ln1w, ln1b, x, h_hi, h_lo,
                                            bq, bk, bv, bg, biasP);
        } else {
            layernorm_split_kernel<<<MROWS, 256>>>(x, part, ln1w + ob, ln1b + ob,
                                                   h_hi, h_lo);
        }

        tc_gemm<<<gemmQKVG, 256, GEMM_SMEM>>>(h_hi, h_lo, qkvg_h + oQW, qkvg_l + oQW,
                                              biasP + (size_t)l * 2048, q,
                                              nullptr, nullptr, nullptr, DD, 2048, 4);

        ret_phase1<<<NRET, 512>>>(q + SZ, q + 2 * SZ, chunkS);
        ret_phase2<<<NRET, 512, RET2_SMEM>>>(q, q + SZ, q + 2 * SZ, chunkS,
                                             gnw + ob, gnb + ob, q + 3 * SZ,
                                             g_hi, g_lo);

        tc_gemm<<<gemmOsp, 256, GEMM_SMEM>>>(g_hi, g_lo, wo_h + oW, wo_l + oW,
                                             bo + ob, x, nullptr, nullptr, part,
                                             DD, DD, 2);

        if (l == 0) {
            wconv_kernel<<<dim3(FFN / 32, DD / 32, LL), wb>>>(w1, w1_h, w1_l, DD, FFN);
            wconv_kernel<<<dim3(DD / 32, FFN / 32, LL), wb>>>(w2, w2_h, w2_l, FFN, DD);
        }

        layernorm_split_kernel<<<MROWS, 256>>>(x, part, ln2w + ob, ln2b + ob,
                                               h_hi, h_lo);

        tc_gemm<<<gemmF1, 256, GEMM_SMEM>>>(h_hi, h_lo, w1_h + oF, w1_l + oF,
                                            b1 + obf, nullptr, ff_hi, ff_lo,
                                            nullptr, DD, FFN, 3);
        if (l + 1 < LL) {
            tc_gemm<<<gemmF2sp, 256, GEMM_SMEM>>>(ff_hi, ff_lo, w2_h + oF, w2_l + oF,
                                                  b2 + ob, x, nullptr, nullptr, part,
                                                  FFN, DD, 2);
        } else {
            tc_gemm<<<gemmF2, 256, GEMM_SMEM>>>(ff_hi, ff_lo, w2_h + oF, w2_l + oF,
                                                b2 + ob, x, nullptr, nullptr, nullptr,
                                                FFN, DD, 2);
        }
    }
}

// round 16
// speedup vs baseline: 1.1064x; 1.0257x over previous
#include <cuda_runtime.h>
#include <cuda_bf16.h>
#include <math.h>
#include <stdint.h>

// ---------------- problem constants ----------------
#define BB   16
#define SS   408
#define DD   512
#define LL   10
#define FFN  2048
#define HH   8
#define DH   64
#define CHK  68
#define NCHUNK (SS/CHK)     // 6
#define MROWS (BB*SS)       // 6528
#define EPS  1e-5f

// ---------------- scratch (no allocations allowed) ----------------
__device__ __align__(16) float g_scratch[(size_t)5 * MROWS * DD];
__device__ __align__(16) float g_chunkS[(size_t)BB * HH * NCHUNK * DH * DH];
__device__ __align__(16) __nv_bfloat16 g_act[(size_t)12 * MROWS * DD];
#define W5  ((size_t)LL * DD * DD)
#define WF  ((size_t)LL * DD * FFN)
__device__ __align__(16) __nv_bfloat16 g_wts[10 * W5 + 4 * WF];
__device__ __align__(16) float g_bias[(size_t)LL * 2048];
__device__ __align__(16) float g_rotcs[SS * 32];
__device__ __align__(16) float g_rotsn[SS * 32];
__device__ __align__(16) float g_gpow[HH * 72];     // gamma_h^j, j=0..68

// ================= PTX helpers (family-portable: sm_80+) =================
__device__ __forceinline__ uint32_t smem_u32(const void* p) {
    uint32_t a;
    asm("{ .reg .u64 t; cvta.to.shared.u64 t, %1; cvt.u32.u64 %0, t; }"
        : "=r"(a) : "l"(p));
    return a;
}
__device__ __forceinline__ void cp16(uint32_t dst, const void* src) {
    asm volatile("cp.async.cg.shared.global [%0], [%1], 16;"
                 :: "r"(dst), "l"(src));
}
#define CP_COMMIT() asm volatile("cp.async.commit_group;" ::: "memory")
#define CP_WAIT(n)  asm volatile("cp.async.wait_group %0;" :: "n"(n) : "memory")

__device__ __forceinline__ void ldsm4(uint32_t* r, uint32_t addr) {
    asm volatile("ldmatrix.sync.aligned.m8n8.x4.shared.b16 {%0,%1,%2,%3}, [%4];"
                 : "=r"(r[0]), "=r"(r[1]), "=r"(r[2]), "=r"(r[3]) : "r"(addr));
}
__device__ __forceinline__ void ldsm4t(uint32_t* r, uint32_t addr) {
    asm volatile("ldmatrix.sync.aligned.m8n8.x4.trans.shared.b16 {%0,%1,%2,%3}, [%4];"
                 : "=r"(r[0]), "=r"(r[1]), "=r"(r[2]), "=r"(r[3]) : "r"(addr));
}
__device__ __forceinline__ void mma_bf16(float* c, const uint32_t* a,
                                         uint32_t b0, uint32_t b1) {
    asm volatile(
        "mma.sync.aligned.m16n8k16.row.col.f32.bf16.bf16.f32 "
        "{%0,%1,%2,%3}, {%4,%5,%6,%7}, {%8,%9}, {%0,%1,%2,%3};"
        : "+f"(c[0]), "+f"(c[1]), "+f"(c[2]), "+f"(c[3])
        : "r"(a[0]), "r"(a[1]), "r"(a[2]), "r"(a[3]), "r"(b0), "r"(b1));
}
__device__ __forceinline__ void bsplit(float f, __nv_bfloat16& h, __nv_bfloat16& l) {
    h = __float2bfloat16(f);
    l = __float2bfloat16(f - __bfloat162float(h));
}

// ------- weight transpose + bf16 hi/lo split: 5 square mats fused -------
__global__ void wconv5_kernel(const float* __restrict__ Wq, const float* __restrict__ Wk,
                              const float* __restrict__ Wv, const float* __restrict__ Wg,
                              const float* __restrict__ Wo,
                              __nv_bfloat16* __restrict__ qkvg_h, __nv_bfloat16* __restrict__ qkvg_l,
                              __nv_bfloat16* __restrict__ wo_h,   __nv_bfloat16* __restrict__ wo_l)
{
    __shared__ float t[32][33];
    int z = blockIdx.z;
    int m = z / LL, l = z - m * LL;
    const float* S = (m == 0) ? Wq : (m == 1) ? Wk : (m == 2) ? Wv : (m == 3) ? Wg : Wo;
    const float* s = S + (size_t)l * DD * DD;
    int n0 = blockIdx.x * 32, k0 = blockIdx.y * 32;
    int tx = threadIdx.x, ty = threadIdx.y;
    #pragma unroll
    for (int r = ty; r < 32; r += 8)
        t[r][tx] = s[(size_t)(k0 + r) * DD + n0 + tx];
    __syncthreads();
    __nv_bfloat16* hi;
    __nv_bfloat16* lo;
    size_t dbase;
    if (m < 4) {
        hi = qkvg_h; lo = qkvg_l;
        dbase = (size_t)l * 2048 * DD + (size_t)m * 512 * DD;
    } else {
        hi = wo_h; lo = wo_l;
        dbase = (size_t)l * DD * DD;
    }
    #pragma unroll
    for (int r = ty; r < 32; r += 8) {
        float x = t[tx][r];
        __nv_bfloat16 h, lw;
        bsplit(x, h, lw);
        size_t o = dbase + (size_t)(n0 + r) * DD + k0 + tx;
        hi[o] = h;
        lo[o] = lw;
    }
}

// ---------------- generic weight transpose (ff mats) --------------
__global__ void wconv_kernel(const float* __restrict__ src,
                             __nv_bfloat16* __restrict__ hi,
                             __nv_bfloat16* __restrict__ lo,
                             int K, int N)
{
    __shared__ float t[32][33];
    int n0 = blockIdx.x * 32, k0 = blockIdx.y * 32;
    const float* s = src + (size_t)blockIdx.z * K * N;
    int tx = threadIdx.x, ty = threadIdx.y;
    #pragma unroll
    for (int r = ty; r < 32; r += 8)
        t[r][tx] = s[(size_t)(k0 + r) * N + n0 + tx];
    __syncthreads();
    size_t dbase = (size_t)blockIdx.z * N * K;
    #pragma unroll
    for (int r = ty; r < 32; r += 8) {
        float x = t[tx][r];
        __nv_bfloat16 h, lw;
        bsplit(x, h, lw);
        size_t o = dbase + (size_t)(n0 + r) * K + k0 + tx;
        hi[o] = h;
        lo[o] = lw;
    }
}

// ---- fused: embed + LN(l0) split + bias pack + rot tables + gpow table ----
__global__ void embed_ln_kernel(const int* __restrict__ tokens,
                                const float* __restrict__ emb,
                                const float* __restrict__ w,
                                const float* __restrict__ b,
                                float* __restrict__ x,
                                __nv_bfloat16* __restrict__ hi,
                                __nv_bfloat16* __restrict__ lo,
                                const float* __restrict__ bq,
                                const float* __restrict__ bk,
                                const float* __restrict__ bv,
                                const float* __restrict__ bg,
                                float* __restrict__ biasPacked)
{
    int row = blockIdx.x;
    int tid = threadIdx.x;                 // 256
    int tok = tokens[row];
    const float* src = emb + (size_t)tok * DD;
    float v0 = src[tid], v1 = src[tid + 256];
    size_t base = (size_t)row * DD;
    x[base + tid]       = v0;
    x[base + tid + 256] = v1;

    float s = v0 + v1, ss = v0*v0 + v1*v1;
    __shared__ float rs[8], rss[8];
    #pragma unroll
    for (int o = 16; o; o >>= 1) {
        s  += __shfl_xor_sync(0xffffffffu, s,  o);
        ss += __shfl_xor_sync(0xffffffffu, ss, o);
    }
    if ((tid & 31) == 0) { rs[tid >> 5] = s; rss[tid >> 5] = ss; }
    __syncthreads();
    float tot = 0.f, tots = 0.f;
    #pragma unroll
    for (int i = 0; i < 8; i++) { tot += rs[i]; tots += rss[i]; }
    float mean = tot * (1.f / DD);
    float var  = tots * (1.f / DD) - mean * mean;
    float rstd = rsqrtf(var + EPS);
    float o0 = (v0 - mean) * rstd * w[tid]       + b[tid];
    float o1 = (v1 - mean) * rstd * w[tid + 256] + b[tid + 256];
    __nv_bfloat16 h0, l0, h1, l1;
    bsplit(o0, h0, l0);
    bsplit(o1, h1, l1);
    hi[base + tid]       = h0;
    hi[base + tid + 256] = h1;
    lo[base + tid]       = l0;
    lo[base + tid + 256] = l1;

    if (row < (LL * 2048) / 512) {
        #pragma unroll
        for (int t = 0; t < 2; t++) {
            int gi = row * 512 + tid + t * 256;
            int l = gi >> 11, r = gi & 2047;
            int wsel = r >> 9, d = r & 511;
            const float* sp = (wsel == 0) ? bq : (wsel == 1) ? bk : (wsel == 2) ? bv : bg;
            biasPacked[gi] = sp[l * 512 + d];
        }
    }
    if (row < SS && tid < 32) {
        float inv = powf(10000.f, -2.f * (float)tid / 64.f);
        float ang = (float)row * inv;
        float sn, cs;
        sincosf(ang, &sn, &cs);
        g_rotcs[row * 32 + tid] = cs;
        g_rotsn[row * 32 + tid] = sn;
    }
    if (row == 0 && tid < HH) {
        float gamma = 1.f - exp2f(-5.f - (float)tid);
        float wv = 1.f;
        for (int j = 0; j <= CHK; j++) {
            g_gpow[tid * 72 + j] = wv;
            wv *= gamma;
        }
    }
}

// ---- layer norm (+ optional split-K partial fold into x) -> bf16 hi/lo ----
__global__ void layernorm_split_kernel(float* __restrict__ x,
                                       const float* __restrict__ addend,
                                       const float* __restrict__ w,
                                       const float* __restrict__ b,
                                       __nv_bfloat16* __restrict__ hi,
                                       __nv_bfloat16* __restrict__ lo)
{
    int row = blockIdx.x;
    int tid = threadIdx.x;                 // 256
    size_t base = (size_t)row * DD;
    float* xr = x + base;
    float v0 = xr[tid], v1 = xr[tid + 256];
    if (addend) {
        const float* ar = addend + base;
        v0 += ar[tid];
        v1 += ar[tid + 256];
        xr[tid]       = v0;
        xr[tid + 256] = v1;
    }
    float s = v0 + v1, ss = v0*v0 + v1*v1;
    __shared__ float rs[8], rss[8];
    #pragma unroll
    for (int o = 16; o; o >>= 1) {
        s  += __shfl_xor_sync(0xffffffffu, s,  o);
        ss += __shfl_xor_sync(0xffffffffu, ss, o);
    }
    if ((tid & 31) == 0) { rs[tid >> 5] = s; rss[tid >> 5] = ss; }
    __syncthreads();
    float tot = 0.f, tots = 0.f;
    #pragma unroll
    for (int i = 0; i < 8; i++) { tot += rs[i]; tots += rss[i]; }
    float mean = tot * (1.f / DD);
    float var  = tots * (1.f / DD) - mean * mean;
    float rstd = rsqrtf(var + EPS);
    float o0 = (v0 - mean) * rstd * w[tid]       + b[tid];
    float o1 = (v1 - mean) * rstd * w[tid + 256] + b[tid + 256];
    __nv_bfloat16 h0, l0, h1, l1;
    bsplit(o0, h0, l0);
    bsplit(o1, h1, l1);
    hi[base + tid]       = h0;
    hi[base + tid + 256] = h1;
    lo[base + tid]       = l0;
    lo[base + tid + 256] = l1;
}

// --- tensor-core GEMM (bf16 3-term, BM=128 BN=64 BK=64, 2 CTA/SM, R11) ---
#define APITCH 144
#define SA_H 0
#define SA_L 18432
#define SB_H 36864
#define SB_L 46080
#define GSTG 55296
#define GEMM_SMEM (2 * GSTG)

__global__ void __launch_bounds__(256, 2)
tc_gemm(const __nv_bfloat16* __restrict__ Ah,
        const __nv_bfloat16* __restrict__ Al,
        const __nv_bfloat16* __restrict__ Bh,
        const __nv_bfloat16* __restrict__ Bl,
        const float* __restrict__ bias,
        float* __restrict__ C,
        __nv_bfloat16* __restrict__ Ch,
        __nv_bfloat16* __restrict__ Cl,
        float* __restrict__ Cpart,
        int K, int N, int epi)
{
    extern __shared__ char sm[];
    uint32_t sb = smem_u32(sm);
    int tid = threadIdx.x;
    int lane = tid & 31, wid = tid >> 5;
    int m0 = blockIdx.y * 128, n0 = blockIdx.x * 64;
    int wm = wid & 3, wn = wid >> 2;      // warp tile 32(M) x 32(N)

    int Keff = K, kbase = 0;
    bool partout = false;
    if (gridDim.z == 2) {
        Keff = K >> 1;
        kbase = blockIdx.z * Keff;
        partout = (blockIdx.z == 1);
    }
    int nst = Keff >> 6;                   // BK = 64

    float acc[8][4];
    #pragma unroll
    for (int i = 0; i < 8; i++)
        #pragma unroll
        for (int j = 0; j < 4; j++) acc[i][j] = 0.f;

    uint32_t rowoff = (uint32_t)((lane & 15) * APITCH + (lane >> 4) * 16);

    auto issue = [&](int s, int buf) {
        uint32_t dst = sb + buf * GSTG;
        int k0 = kbase + (s << 6);
        #pragma unroll
        for (int it = 0; it < 4; it++) {
            int c = tid + it * 256;          // A: 128 rows x 8 segs
            int row = c >> 3, seg = c & 7;
            uint32_t doff = (uint32_t)(row * APITCH + seg * 16);
            size_t aoff = (size_t)(m0 + row) * K + k0 + seg * 8;
            cp16(dst + SA_H + doff, Ah + aoff);
            cp16(dst + SA_L + doff, Al + aoff);
        }
        #pragma unroll
        for (int it = 0; it < 2; it++) {
            int c = tid + it * 256;          // B: 64 rows x 8 segs
            int row = c >> 3, seg = c & 7;
            uint32_t doff = (uint32_t)(row * APITCH + seg * 16);
            size_t boff = (size_t)(n0 + row) * K + k0 + seg * 8;
            cp16(dst + SB_H + doff, Bh + boff);
            cp16(dst + SB_L + doff, Bl + boff);
        }
    };

    issue(0, 0);
    CP_COMMIT();

    for (int s = 0; s < nst; s++) {
        int buf = s & 1;
        if (s + 1 < nst) {
            issue(s + 1, buf ^ 1);
            CP_COMMIT();
            CP_WAIT(1);
        } else {
            CP_WAIT(0);
        }
        __syncthreads();

        uint32_t base  = sb + buf * GSTG;
        uint32_t abase = base + (uint32_t)(wm * 32 * APITCH) + rowoff;
        uint32_t bbase = base + SB_H + (uint32_t)(wn * 32 * APITCH) + rowoff;

        #pragma unroll
        for (int kst = 0; kst < 4; kst++) {
            uint32_t koff = (uint32_t)(kst * 32);
            uint32_t bh[2][4], bl[2][4];
            #pragma unroll
            for (int nb = 0; nb < 2; nb++) {
                ldsm4(bh[nb], bbase + nb * (16 * APITCH) + koff);
                ldsm4(bl[nb], bbase + (SB_L - SB_H) + nb * (16 * APITCH) + koff);
            }
            #pragma unroll
            for (int mt = 0; mt < 2; mt++) {
                uint32_t ah[4], al[4];
                ldsm4(ah, abase + SA_H + mt * (16 * APITCH) + koff);
                ldsm4(al, abase + SA_L + mt * (16 * APITCH) + koff);
                #pragma unroll
                for (int nt = 0; nt < 4; nt++)
                    mma_bf16(acc[mt * 4 + nt], ah,
                             bh[nt >> 1][nt & 1], bh[nt >> 1][(nt & 1) + 2]);
                #pragma unroll
                for (int nt = 0; nt < 4; nt++)
                    mma_bf16(acc[mt * 4 + nt], al,
                             bh[nt >> 1][nt & 1], bh[nt >> 1][(nt & 1) + 2]);
                #pragma unroll
                for (int nt = 0; nt < 4; nt++)
                    mma_bf16(acc[mt * 4 + nt], ah,
                             bl[nt >> 1][nt & 1], bl[nt >> 1][(nt & 1) + 2]);
            }
        }
        __syncthreads();
    }

    // -------- epilogue --------
    int r_lane = lane >> 2;
    int c_lane = (lane & 3) * 2;

    if (partout) {
        #pragma unroll
        for (int mt = 0; mt < 2; mt++) {
            int r0 = m0 + wm * 32 + mt * 16 + r_lane;
            int r1 = r0 + 8;
            #pragma unroll
            for (int nt = 0; nt < 4; nt++) {
                float* a = acc[mt * 4 + nt];
                int nn = n0 + wn * 32 + nt * 8 + c_lane;
                *(float2*)(Cpart + (size_t)r0 * N + nn) = make_float2(a[0], a[1]);
                *(float2*)(Cpart + (size_t)r1 * N + nn) = make_float2(a[2], a[3]);
            }
        }
        return;
    }

    bool fused = (epi == 4);
    int which = n0 >> 9;
    float* Cb = C;
    int ldc = N, ncol0 = n0;
    if (fused) {
        Cb = C + (size_t)which * ((size_t)MROWS * 512);
        ldc = 512;
        ncol0 = n0 & 511;
    }
    bool dosilu = (epi == 1) || (epi == 3) || (fused && which == 3);

    #pragma unroll
    for (int mt = 0; mt < 2; mt++) {
        int r0 = m0 + wm * 32 + mt * 16 + r_lane;
        int r1 = r0 + 8;
        #pragma unroll
        for (int nt = 0; nt < 4; nt++) {
            float* a = acc[mt * 4 + nt];
            int ncb = wn * 32 + nt * 8 + c_lane;
            float b0 = bias[n0 + ncb], b1 = bias[n0 + ncb + 1];
            float x0 = a[0] + b0, x1 = a[1] + b1;
            float y0 = a[2] + b0, y1 = a[3] + b1;
            if (dosilu) {
                x0 = x0 / (1.f + expf(-x0));
                x1 = x1 / (1.f + expf(-x1));
                y0 = y0 / (1.f + expf(-y0));
                y1 = y1 / (1.f + expf(-y1));
            }
            int nn = ncol0 + ncb;
            if (epi == 3) {
                __nv_bfloat162 h0 = __floats2bfloat162_rn(x0, x1);
                __nv_bfloat162 h1 = __floats2bfloat162_rn(y0, y1);
                float2 f0 = __bfloat1622float2(h0);
                float2 f1 = __bfloat1622float2(h1);
                __nv_bfloat162 l0 = __floats2bfloat162_rn(x0 - f0.x, x1 - f0.y);
                __nv_bfloat162 l1 = __floats2bfloat162_rn(y0 - f1.x, y1 - f1.y);
                *(__nv_bfloat162*)(Ch + (size_t)r0 * N + nn) = h0;
                *(__nv_bfloat162*)(Cl + (size_t)r0 * N + nn) = l0;
                *(__nv_bfloat162*)(Ch + (size_t)r1 * N + nn) = h1;
                *(__nv_bfloat162*)(Cl + (size_t)r1 * N + nn) = l1;
            } else {
                float* p0 = Cb + (size_t)r0 * ldc + nn;
                float* p1 = Cb + (size_t)r1 * ldc + nn;
                if (epi == 2) {
                    float2 c0 = *(float2*)p0;
                    float2 c1 = *(float2*)p1;
                    x0 += c0.x; x1 += c0.y;
                    y0 += c1.x; y1 += c1.y;
                }
                *(float2*)p0 = make_float2(x0, x1);
                *(float2*)p1 = make_float2(y0, y1);
            }
        }
    }
}

// == retention phase 1 (HMMA, [j][d] smem layout + ldmatrix.trans) ==
// Conflict-free smem stores; trans-ldmatrix reproduces the same fragments.
#define P1P 72      // bf16 elements per j-row (144 B, 16B-aligned)
__global__ void __launch_bounds__(512)
ret_phase1(const float* __restrict__ k, const float* __restrict__ v,
           float* __restrict__ chunkS)
{
    __shared__ __nv_bfloat16 kth[80 * P1P], ktl[80 * P1P];
    __shared__ __nv_bfloat16 vth[80 * P1P], vtl[80 * P1P];
    __shared__ float gpow[CHK + 1];

    int z  = blockIdx.x;
    int bh = z / NCHUNK, c = z - bh * NCHUNK;
    int b  = bh >> 3, hh = bh & 7;
    int tid = threadIdx.x;
    if (tid <= CHK) gpow[tid] = g_gpow[hh * 72 + tid];
    __nv_bfloat16 z16 = __float2bfloat16(0.f);
    // zero pad rows j = 68..79 (12 * 72 = 864 elems per tensor)
    #pragma unroll
    for (int it = 0; it < 2; it++) {
        int t = tid + it * 512;
        if (t < 12 * P1P) {
            int idx = 68 * P1P + t;
            kth[idx] = z16; ktl[idx] = z16;
            vth[idx] = z16; vtl[idx] = z16;
        }
    }
    __syncthreads();

    int base = ((b * SS + c * CHK) * HH + hh) * DH;
    #pragma unroll
    for (int it = 0; it < 9; it++) {
        int i = tid + it * 512;
        if (i < CHK * DH) {
            int r = i >> 6, d = i & 63;
            int g = base + r * DD + d;
            int spos = c * CHK + r;
            int j = d & 31;
            float cs = g_rotcs[spos * 32 + j];
            float sn = g_rotsn[spos * 32 + j];
            float ka = k[g];
            float kb = (d < 32) ? -k[g + 32] : k[g - 32];
            float kv = (ka * cs + kb * sn) * 0.125f * gpow[CHK - 1 - r];
            __nv_bfloat16 h, l;
            bsplit(kv, h, l);
            kth[r * P1P + d] = h;          // conflict-free (consecutive d)
            ktl[r * P1P + d] = l;
            float vv = v[g];
            bsplit(vv, h, l);
            vth[r * P1P + d] = h;
            vtl[r * P1P + d] = l;
        }
    }
    __syncthreads();

    uint32_t kthA = smem_u32(kth), ktlA = smem_u32(ktl);
    uint32_t vthA = smem_u32(vth), vtlA = smem_u32(vtl);
    int lane = tid & 31, wid = tid >> 5;   // 16 warps = 16 output tiles
    // trans-ldmatrix addressing: lane -> stored j-row + d col-half
    uint32_t troff = (uint32_t)((((lane & 7) + (lane >> 4) * 8) * (P1P * 2))
                                + ((lane >> 3) & 1) * 16);
    float* out = chunkS + (size_t)z * (DH * DH);

    {
        int mt = wid >> 2, nb = wid & 3;
        float acc[2][4] = {};
        #pragma unroll
        for (int kst = 0; kst < 5; kst++) {
            uint32_t jb = (uint32_t)(kst * 16 * (P1P * 2));
            uint32_t ah[4], al[4], bh4[4], bl4[4];
            ldsm4t(ah, kthA + jb + mt * 32 + troff);
            ldsm4t(al, ktlA + jb + mt * 32 + troff);
            ldsm4t(bh4, vthA + jb + nb * 32 + troff);
            ldsm4t(bl4, vtlA + jb + nb * 32 + troff);
            #pragma unroll
            for (int half = 0; half < 2; half++) {
                mma_bf16(acc[half], ah, bh4[half], bh4[half + 2]);
                mma_bf16(acc[half], al, bh4[half], bh4[half + 2]);
                mma_bf16(acc[half], ah, bl4[half], bl4[half + 2]);
            }
        }
        int r0 = mt * 16 + (lane >> 2);
        #pragma unroll
        for (int half = 0; half < 2; half++) {
            int c0 = nb * 16 + half * 8 + (lane & 3) * 2;
            out[r0 * 64 + c0]           = acc[half][0];
            out[r0 * 64 + c0 + 1]       = acc[half][1];
            out[(r0 + 8) * 64 + c0]     = acc[half][2];
            out[(r0 + 8) * 64 + c0 + 1] = acc[half][3];
        }
    }
}

// ===== retention phase 2 (FFMA overlay, 512 thr) + FUSED gnorm*gate =====
#define KT_PITCH 68
#define RET2_FLOATS (2 * CHK * DH + DH * DH + 4624)
__global__ void __launch_bounds__(512)
ret_phase2(const float* __restrict__ q, const float* __restrict__ k,
           const float* __restrict__ v, const float* __restrict__ chunkS,
           const float* __restrict__ gnw, const float* __restrict__ gnb,
           const float* __restrict__ gate,
           __nv_bfloat16* __restrict__ ghi, __nv_bfloat16* __restrict__ glo)
{
    extern __shared__ float smf[];
    float* sq    = smf;
    float* sv    = sq + CHK * DH;
    float* st    = sv + CHK * DH;
    float* skT   = st + DH * DH;
    float* inner = skT;
    __shared__ float gpow[CHK + 1];

    int z  = blockIdx.x;
    int bh = z / NCHUNK, c = z - bh * NCHUNK;
    int b  = bh >> 3, hh = bh & 7;
    int tid = threadIdx.x;
    if (tid <= CHK) gpow[tid] = g_gpow[hh * 72 + tid];
    __syncthreads();
    float gamma = gpow[1];
    float chunk_dec = gpow[CHK];

    int base = ((b * SS + c * CHK) * HH + hh) * DH;
    #pragma unroll
    for (int it = 0; it < 9; it++) {
        int i = tid + it * 512;
        if (i < CHK * DH) {
            int r = i >> 6, d = i & 63;
            int g = base + r * DD + d;
            int spos = c * CHK + r;
            int j = d & 31;
            float cs = g_rotcs[spos * 32 + j];
            float sn = g_rotsn[spos * 32 + j];
            float qa = q[g], ka = k[g];
            float qb, kb;
            if (d < 32) { qb = -q[g + 32]; kb = -k[g + 32]; }
            else        { qb =  q[g - 32]; kb =  k[g - 32]; }
            sq[i] = qa * cs + qb * sn;
            skT[d * KT_PITCH + r] = (ka * cs + kb * sn) * 0.125f;
            sv[i] = v[g];
        }
    }
    {
        const float* Sbase = chunkS + (size_t)(bh * NCHUNK) * (DH * DH);
        #pragma unroll
        for (int g4 = 0; g4 < 2; g4++) {
            int idx = tid * 8 + g4 * 4;
            float4 acc = make_float4(0.f, 0.f, 0.f, 0.f);
            float w = 1.f;
            for (int cc = c - 1; cc >= 0; cc--) {
                float4 sv4 = *(const float4*)(Sbase + (size_t)cc * (DH * DH) + idx);
                acc.x += w * sv4.x; acc.y += w * sv4.y;
                acc.z += w * sv4.z; acc.w += w * sv4.w;
                w *= chunk_dec;
            }
            *(float4*)(st + idx) = acc;
        }
    }
    __syncthreads();

    float ir[3][4];
    #pragma unroll
    for (int it = 0; it < 3; it++) {
        int e = tid + it * 512;
        if (e < CHK * 17) {
            int i = e / 17, jg = e - i * 17;
            int j0 = jg * 4;
            float4 s = make_float4(0.f, 0.f, 0.f, 0.f);
            if (i >= j0) {
                const float* qi = sq + i * DH;
                #pragma unroll 4
                for (int d4 = 0; d4 < DH; d4 += 4) {
                    float4 qv = *(const float4*)(qi + d4);
                    float4 k0 = *(const float4*)(skT + (d4 + 0) * KT_PITCH + j0);
                    float4 k1 = *(const float4*)(skT + (d4 + 1) * KT_PITCH + j0);
                    float4 k2 = *(const float4*)(skT + (d4 + 2) * KT_PITCH + j0);
                    float4 k3 = *(const float4*)(skT + (d4 + 3) * KT_PITCH + j0);
                    s.x += qv.x*k0.x + qv.y*k1.x + qv.z*k2.x + qv.w*k3.x;
                    s.y += qv.x*k0.y + qv.y*k1.y + qv.z*k2.y + qv.w*k3.y;
                    s.z += qv.x*k0.z + qv.y*k1.z + qv.z*k2.z + qv.w*k3.z;
                    s.w += qv.x*k0.w + qv.y*k1.w + qv.z*k2.w + qv.w*k3.w;
                }
            }
            ir[it][0] = s.x; ir[it][1] = s.y;
            ir[it][2] = s.z; ir[it][3] = s.w;
        }
    }
    __syncthreads();
    #pragma unroll
    for (int it = 0; it < 3; it++) {
        int e = tid + it * 512;
        if (e < CHK * 17) {
            int i = e / 17, jg = e - i * 17;
            int j0 = jg * 4;
            float* out = inner + i * CHK + j0;
            out[0] = (i >= j0)     ? ir[it][0] * gpow[i - j0]     : 0.f;
            out[1] = (i >= j0 + 1) ? ir[it][1] * gpow[i - j0 - 1] : 0.f;
            out[2] = (i >= j0 + 2) ? ir[it][2] * gpow[i - j0 - 2] : 0.f;
            out[3] = (i >= j0 + 3) ? ir[it][3] * gpow[i - j0 - 3] : 0.f;
        }
    }
    __syncthreads();

    #pragma unroll
    for (int kk = 0; kk < 3; kk++) {
        int e = tid + kk * 512;
        if (e >= CHK * 16) break;
        int i = e >> 4, d4 = (e & 15) << 2;
        float4 acc = make_float4(0.f, 0.f, 0.f, 0.f);
        const float* in_i = inner + i * CHK;
        for (int j = 0; j <= i; j++) {
            float w = in_i[j];
            float4 vv = *(const float4*)(sv + j * DH + d4);
            acc.x += w * vv.x; acc.y += w * vv.y;
            acc.z += w * vv.z; acc.w += w * vv.w;
        }
        float4 a2 = make_float4(0.f, 0.f, 0.f, 0.f);
        const float* qi = sq + i * DH;
        #pragma unroll 8
        for (int ee = 0; ee < DH; ee++) {
            float qv = qi[ee];
            float4 sr = *(const float4*)(st + ee * DH + d4);
            a2.x += qv * sr.x; a2.y += qv * sr.y;
            a2.z += qv * sr.z; a2.w += qv * sr.w;
        }
        float cd = gamma * gpow[i];
        acc.x += a2.x * cd; acc.y += a2.y * cd;
        acc.z += a2.z * cd; acc.w += a2.w * cd;

        float lsum = acc.x + acc.y + acc.z + acc.w;
        float lss  = acc.x*acc.x + acc.y*acc.y + acc.z*acc.z + acc.w*acc.w;
        #pragma unroll
        for (int o = 8; o; o >>= 1) {
            lsum += __shfl_xor_sync(0xffffffffu, lsum, o);
            lss  += __shfl_xor_sync(0xffffffffu, lss,  o);
        }
        float mean = lsum * (1.f / DH);
        float var  = lss * (1.f / DH) - mean * mean;
        float rstd = rsqrtf(var + EPS);
        int wi = hh * DH + d4;
        float4 gw = *(const float4*)(gnw + wi);
        float4 gb = *(const float4*)(gnb + wi);
        int gidx = base + i * DD + d4;
        float4 gt = *(const float4*)(gate + gidx);
        float p0 = gt.x * ((acc.x - mean) * rstd * gw.x + gb.x);
        float p1 = gt.y * ((acc.y - mean) * rstd * gw.y + gb.y);
        float p2 = gt.z * ((acc.z - mean) * rstd * gw.z + gb.z);
        float p3 = gt.w * ((acc.w - mean) * rstd * gw.w + gb.w);
        __nv_bfloat162 h0 = __floats2bfloat162_rn(p0, p1);
        __nv_bfloat162 h1 = __floats2bfloat162_rn(p2, p3);
        float2 f0 = __bfloat1622float2(h0);
        float2 f1 = __bfloat1622float2(h1);
        __nv_bfloat162 l0 = __floats2bfloat162_rn(p0 - f0.x, p1 - f0.y);
        __nv_bfloat162 l1 = __floats2bfloat162_rn(p2 - f1.x, p3 - f1.y);
        *(__nv_bfloat162*)(ghi + gidx)     = h0;
        *(__nv_bfloat162*)(ghi + gidx + 2) = h1;
        *(__nv_bfloat162*)(glo + gidx)     = l0;
        *(__nv_bfloat162*)(glo + gidx + 2) = l1;
    }
}

// ---------------- host orchestration ----------------
extern "C" void kernel_launch(void* const* d_in, const int* in_sizes, int n_in,
                              void* d_out, int out_size)
{
    const int*   tokens = (const int*)  d_in[0];
    const float* emb    = (const float*)d_in[1];
    const float* Wq = (const float*)d_in[2],  * bq = (const float*)d_in[3];
    const float* Wk = (const float*)d_in[4],  * bk = (const float*)d_in[5];
    const float* Wv = (const float*)d_in[6],  * bv = (const float*)d_in[7];
    const float* Wg = (const float*)d_in[8],  * bg = (const float*)d_in[9];
    const float* Wo = (const float*)d_in[10], * bo = (const float*)d_in[11];
    const float* gnw  = (const float*)d_in[12], * gnb  = (const float*)d_in[13];
    const float* ln1w = (const float*)d_in[14], * ln1b = (const float*)d_in[15];
    const float* ln2w = (const float*)d_in[16], * ln2b = (const float*)d_in[17];
    const float* w1 = (const float*)d_in[18], * b1 = (const float*)d_in[19];
    const float* w2 = (const float*)d_in[20], * b2 = (const float*)d_in[21];

    float* x = (float*)d_out;

    float* fb = nullptr;
    cudaGetSymbolAddress((void**)&fb, g_scratch);
    const size_t SZ = (size_t)MROWS * DD;
    float* q    = fb;                        // q,k,v,gate consecutive (epi4!)
    float* part = fb + 4 * SZ;               // split-K partial buffer

    float* chunkS = nullptr;
    cudaGetSymbolAddress((void**)&chunkS, g_chunkS);

    __nv_bfloat16* ab = nullptr;
    cudaGetSymbolAddress((void**)&ab, g_act);
    __nv_bfloat16* h_hi  = ab;
    __nv_bfloat16* h_lo  = ab + SZ;
    __nv_bfloat16* g_hi  = ab + 2 * SZ;
    __nv_bfloat16* g_lo  = ab + 3 * SZ;
    __nv_bfloat16* ff_hi = ab + 4 * SZ;
    __nv_bfloat16* ff_lo = ab + 8 * SZ;

    __nv_bfloat16* wts = nullptr;
    cudaGetSymbolAddress((void**)&wts, g_wts);
    __nv_bfloat16* qkvg_h = wts;             // [L][2048][512]
    __nv_bfloat16* qkvg_l = wts + 4 * W5;
    __nv_bfloat16* wo_h   = wts + 8 * W5;
    __nv_bfloat16* wo_l   = wts + 9 * W5;
    __nv_bfloat16* w1_h   = wts + 10 * W5;
    __nv_bfloat16* w1_l   = wts + 10 * W5 + WF;
    __nv_bfloat16* w2_h   = wts + 10 * W5 + 2 * WF;
    __nv_bfloat16* w2_l   = wts + 10 * W5 + 3 * WF;

    float* biasP = nullptr;
    cudaGetSymbolAddress((void**)&biasP, g_bias);

    const int RET2_SMEM = RET2_FLOATS * (int)sizeof(float);
    cudaFuncSetAttribute(ret_phase2,
                         cudaFuncAttributeMaxDynamicSharedMemorySize, RET2_SMEM);
    cudaFuncSetAttribute(tc_gemm,
                         cudaFuncAttributeMaxDynamicSharedMemorySize, GEMM_SMEM);

    dim3 wb(32, 8);
    dim3 gemmQKVG(2048 / 64, MROWS / 128);      // (32, 51)
    dim3 gemmOsp(DD / 64, MROWS / 128, 2);      // (8, 51, 2)  split-K
    dim3 gemmF1(FFN / 64, MROWS / 128);         // (32, 51)
    dim3 gemmF2sp(DD / 64, MROWS / 128, 2);     // (8, 51, 2)  split-K
    dim3 gemmF2(DD / 64, MROWS / 128);          // (8, 51)     last layer
    const int NRET = BB * HH * NCHUNK;          // 768

    for (int l = 0; l < LL; l++) {
        const size_t oQW = (size_t)l * 2048 * DD;
        const size_t oW  = (size_t)l * DD * DD;
        const size_t oF  = (size_t)l * DD * FFN;
        const size_t ob  = (size_t)l * DD;
        const size_t obf = (size_t)l * FFN;

        if (l == 0) {
            wconv5_kernel<<<dim3(16, 16, 5 * LL), wb>>>(Wq, Wk, Wv, Wg, Wo,
                                                        qkvg_h, qkvg_l, wo_h, wo_l);
            embed_ln_kernel<<<MROWS, 256>>>(tokens, emb, ln1w, ln1b, x, h_hi, h_lo,
                                            bq, bk, bv, bg, biasP);
            // moved before qkvg so the profiled launch (#3) is tc_gemm
            wconv_kernel<<<dim3(FFN / 32, DD / 32, LL), wb>>>(w1, w1_h, w1_l, DD, FFN);
        } else {
            layernorm_split_kernel<<<MROWS, 256>>>(x, part, ln1w + ob, ln1b + ob,
                                                   h_hi, h_lo);
        }

        tc_gemm<<<gemmQKVG, 256, GEMM_SMEM>>>(h_hi, h_lo, qkvg_h + oQW, qkvg_l + oQW,
                                              biasP + (size_t)l * 2048, q,
                                              nullptr, nullptr, nullptr, DD, 2048, 4);

        ret_phase1<<<NRET, 512>>>(q + SZ, q + 2 * SZ, chunkS);
        ret_phase2<<<NRET, 512, RET2_SMEM>>>(q, q + SZ, q + 2 * SZ, chunkS,
                                             gnw + ob, gnb + ob, q + 3 * SZ,
                                             g_hi, g_lo);

        tc_gemm<<<gemmOsp, 256, GEMM_SMEM>>>(g_hi, g_lo, wo_h + oW, wo_l + oW,
                                             bo + ob, x, nullptr, nullptr, part,
                                             DD, DD, 2);

        if (l == 0) {
            wconv_kernel<<<dim3(DD / 32, FFN / 32, LL), wb>>>(w2, w2_h, w2_l, FFN, DD);
        }

        layernorm_split_kernel<<<MROWS, 256>>>(x, part, ln2w + ob, ln2b + ob,
                                               h_hi, h_lo);

        tc_gemm<<<gemmF1, 256, GEMM_SMEM>>>(h_hi, h_lo, w1_h + oF, w1_l + oF,
                                            b1 + obf, nullptr, ff_hi, ff_lo,
                                            nullptr, DD, FFN, 3);
        if (l + 1 < LL) {
            tc_gemm<<<gemmF2sp, 256, GEMM_SMEM>>>(ff_hi, ff_lo, w2_h + oF, w2_l + oF,
                                                  b2 + ob, x, nullptr, nullptr, part,
                                                  FFN, DD, 2);
        } else {
            tc_gemm<<<gemmF2, 256, GEMM_SMEM>>>(ff_hi, ff_lo, w2_h + oF, w2_l + oF,
                                                b2 + ob, x, nullptr, nullptr, nullptr,
                                                FFN, DD, 2);
        }
    }
}